// round 9
// baseline (speedup 1.0000x reference)
#include <cuda_runtime.h>
#include <cuda_bf16.h>
#include <math.h>

// ---------------- problem constants ----------------
#define BB     2
#define LL     1024
#define DD     1024
#define HH     16
#define FDIM   512
#define NLAYER 4
#define NVOC   5000
#define DFF    4096
#define SS     1026            // seqlen = 1 (graph) + 1 (sos) + L
#define MROWS  (BB*SS)         // 2052
#define OUTROWS (BB*(SS-1))    // 2050 output rows (skip graph row)

#define QKV_OFF (BB*SS*DD)
#define FFN_OFF (BB*SS*DFF)

// ---------------- scratch (device globals; no allocation allowed) ----------------
__device__ float g_h  [BB*SS*DD];
__device__ float g_x  [BB*SS*DD];
__device__ float g_qkv[3*BB*SS*DD];
__device__ float g_att[BB*SS*DD];
__device__ float g_ffn[2*BB*SS*DFF];

// ---------------- tf32 helpers ----------------
__device__ __forceinline__ unsigned tf32cvt(float x) {
    unsigned r;
    asm("cvt.rna.tf32.f32 %0, %1;" : "=r"(r) : "f"(x));
    return r;
}
__device__ __forceinline__ void mma_tf32(float* d, const unsigned* a, const unsigned* b) {
    asm volatile(
        "mma.sync.aligned.m16n8k8.row.col.f32.tf32.tf32.f32 "
        "{%0,%1,%2,%3}, {%4,%5,%6,%7}, {%8,%9}, {%0,%1,%2,%3};"
        : "+f"(d[0]), "+f"(d[1]), "+f"(d[2]), "+f"(d[3])
        : "r"(a[0]), "r"(a[1]), "r"(a[2]), "r"(a[3]), "r"(b[0]), "r"(b[1]));
}
__device__ __forceinline__ void ldsm4(unsigned* f, unsigned saddr) {
    asm volatile("ldmatrix.sync.aligned.m8n8.x4.shared.b16 {%0,%1,%2,%3}, [%4];"
        : "=r"(f[0]), "=r"(f[1]), "=r"(f[2]), "=r"(f[3]) : "r"(saddr));
}

// ---------------- TF32 tensor-core GEMM ----------------
// C[M,N] (op) A[M,K] @ W[K,N], K % 16 == 0, N % 4 == 0.
// mode 0: C = A@W        mode 1: C = A@W + E (bias, len N)       mode 2: C += A@W
// aop 0: normal A        aop 1: logits row remap                 aop 2: A = silu(A)*A2
// blockIdx.z selects (W0/W1/W2p, C0/C1/C2p).
#define AST 20    // As row stride in tf32 (80B: LDSM rows land on 8 distinct bank-quads)
#define BST 136   // Bs row stride (scalar LDS conflict-free)

__global__ void __launch_bounds__(256, 2)
gemm_tc(const float* __restrict__ A, const float* __restrict__ A2,
        const float* __restrict__ W0, const float* __restrict__ W1, const float* __restrict__ W2p,
        float* __restrict__ C0, float* __restrict__ C1, float* __restrict__ C2p,
        const float* __restrict__ E, int M, int N, int K, int mode, int aop)
{
    __shared__ unsigned As[2][128][AST];
    __shared__ unsigned Bs[2][16][BST];

    const float* W = (blockIdx.z == 0) ? W0 : (blockIdx.z == 1) ? W1 : W2p;
    float*       C = (blockIdx.z == 0) ? C0 : (blockIdx.z == 1) ? C1 : C2p;

    const int tid = threadIdx.x;
    const int bm = blockIdx.y * 128;
    const int bn = blockIdx.x * 128;

    // ---- gmem load indices ----
    const int a_r0 = tid >> 2;            // 0..63
    const int a_c  = (tid & 3) << 2;      // k offset 0/4/8/12
    const int b_k0 = tid >> 5;            // 0..7
    const int b_c  = (tid & 31) << 2;

    int am0 = bm + a_r0, am1 = bm + a_r0 + 64;
    const bool av0 = am0 < M, av1 = am1 < M;
    if (aop == 1) {
        if (av0) am0 = (am0 / 1025) * SS + 1 + (am0 % 1025);
        if (av1) am1 = (am1 / 1025) * SS + 1 + (am1 % 1025);
    }
    const float* ap0 = A + (size_t)am0 * K + a_c;
    const float* ap1 = A + (size_t)am1 * K + a_c;
    const float* aq0 = A2 + (size_t)am0 * K + a_c;
    const float* aq1 = A2 + (size_t)am1 * K + a_c;
    const float* bp0 = W + (size_t)b_k0 * N + bn + b_c;
    const float* bp1 = W + (size_t)(b_k0 + 8) * N + bn + b_c;
    const bool bv = (bn + b_c) < N;

    // ---- warp / fragment indices ----
    const int wid = tid >> 5, lane = tid & 31;
    const int wm = (wid >> 2) * 64;       // warp row base
    const int wn = (wid & 3) * 32;        // warp col base
    const int lm = lane >> 2;             // 0..7
    const int lk = lane & 3;              // 0..3

    // LDSM per-lane source: group g = lane>>3, row-in-mat lr = lane&7
    const int lds_row = (lane & 7) + ((lane >> 3) & 1) * 8;   // + r0
    const int lds_bcol = ((lane >> 4) & 1) * 16;              // byte col offset (+kb*4)
    const unsigned asBase0 = (unsigned)__cvta_generic_to_shared(&As[0][0][0]);
    const unsigned asBase1 = (unsigned)__cvta_generic_to_shared(&As[1][0][0]);

    float acc[4][4][4];
    #pragma unroll
    for (int i = 0; i < 4; i++)
        #pragma unroll
        for (int j = 0; j < 4; j++)
            #pragma unroll
            for (int r = 0; r < 4; r++) acc[i][j][r] = 0.f;

    const int nkt = K >> 4;
    float4 a4_0, a4_1, b4_0, b4_1;

    auto loadA = [&](const float* p, const float* q, bool valid) -> float4 {
        if (!valid) return make_float4(0.f, 0.f, 0.f, 0.f);
        float4 v = *(const float4*)p;
        if (aop == 2) {
            float4 u = *(const float4*)q;
            v.x = v.x / (1.f + __expf(-v.x)) * u.x;
            v.y = v.y / (1.f + __expf(-v.y)) * u.y;
            v.z = v.z / (1.f + __expf(-v.z)) * u.z;
            v.w = v.w / (1.f + __expf(-v.w)) * u.w;
        }
        return v;
    };

    // preload tile 0
    a4_0 = loadA(ap0, aq0, av0);
    a4_1 = loadA(ap1, aq1, av1);
    b4_0 = bv ? *(const float4*)bp0 : make_float4(0.f,0.f,0.f,0.f);
    b4_1 = bv ? *(const float4*)bp1 : make_float4(0.f,0.f,0.f,0.f);

    int buf = 0;
    {
        uint4 ua0 = { tf32cvt(a4_0.x), tf32cvt(a4_0.y), tf32cvt(a4_0.z), tf32cvt(a4_0.w) };
        uint4 ua1 = { tf32cvt(a4_1.x), tf32cvt(a4_1.y), tf32cvt(a4_1.z), tf32cvt(a4_1.w) };
        uint4 ub0 = { tf32cvt(b4_0.x), tf32cvt(b4_0.y), tf32cvt(b4_0.z), tf32cvt(b4_0.w) };
        uint4 ub1 = { tf32cvt(b4_1.x), tf32cvt(b4_1.y), tf32cvt(b4_1.z), tf32cvt(b4_1.w) };
        *(uint4*)&As[0][a_r0     ][a_c] = ua0;
        *(uint4*)&As[0][a_r0 + 64][a_c] = ua1;
        *(uint4*)&Bs[0][b_k0     ][b_c] = ub0;
        *(uint4*)&Bs[0][b_k0 + 8 ][b_c] = ub1;
    }
    __syncthreads();

    for (int kt = 0; kt < nkt; kt++) {
        if (kt + 1 < nkt) {
            ap0 += 16; ap1 += 16; aq0 += 16; aq1 += 16;
            bp0 += (size_t)16 * N; bp1 += (size_t)16 * N;
            a4_0 = loadA(ap0, aq0, av0);
            a4_1 = loadA(ap1, aq1, av1);
            b4_0 = bv ? *(const float4*)bp0 : make_float4(0.f,0.f,0.f,0.f);
            b4_1 = bv ? *(const float4*)bp1 : make_float4(0.f,0.f,0.f,0.f);
        }

        const unsigned asb = buf ? asBase1 : asBase0;
        #pragma unroll
        for (int ks = 0; ks < 2; ks++) {
            const int kb = ks * 8;
            unsigned af[4][4], bf[4][2];
            #pragma unroll
            for (int mt = 0; mt < 4; mt++) {
                const int r = wm + mt * 16 + lds_row;
                ldsm4(af[mt], asb + (unsigned)(r * (AST*4) + kb * 4 + lds_bcol));
            }
            #pragma unroll
            for (int nt = 0; nt < 4; nt++) {
                const int c = wn + nt * 8 + lm;
                bf[nt][0] = Bs[buf][kb + lk    ][c];
                bf[nt][1] = Bs[buf][kb + lk + 4][c];
            }
            #pragma unroll
            for (int mt = 0; mt < 4; mt++)
                #pragma unroll
                for (int nt = 0; nt < 4; nt++)
                    mma_tf32(acc[mt][nt], af[mt], bf[nt]);
        }

        if (kt + 1 < nkt) {
            const int nb = buf ^ 1;
            uint4 ua0 = { tf32cvt(a4_0.x), tf32cvt(a4_0.y), tf32cvt(a4_0.z), tf32cvt(a4_0.w) };
            uint4 ua1 = { tf32cvt(a4_1.x), tf32cvt(a4_1.y), tf32cvt(a4_1.z), tf32cvt(a4_1.w) };
            uint4 ub0 = { tf32cvt(b4_0.x), tf32cvt(b4_0.y), tf32cvt(b4_0.z), tf32cvt(b4_0.w) };
            uint4 ub1 = { tf32cvt(b4_1.x), tf32cvt(b4_1.y), tf32cvt(b4_1.z), tf32cvt(b4_1.w) };
            *(uint4*)&As[nb][a_r0     ][a_c] = ua0;
            *(uint4*)&As[nb][a_r0 + 64][a_c] = ua1;
            *(uint4*)&Bs[nb][b_k0     ][b_c] = ub0;
            *(uint4*)&Bs[nb][b_k0 + 8 ][b_c] = ub1;
        }
        __syncthreads();
        buf ^= 1;
    }

    // ---- epilogue ----
    #pragma unroll
    for (int mt = 0; mt < 4; mt++) {
        #pragma unroll
        for (int rr = 0; rr < 2; rr++) {
            const int m = bm + wm + mt * 16 + lm + rr * 8;
            if (m >= M) continue;
            const size_t base = (size_t)m * N;
            #pragma unroll
            for (int nt = 0; nt < 4; nt++) {
                const int c = bn + wn + nt * 8 + 2 * lk;
                if (c >= N) continue;
                float v0 = acc[mt][nt][rr * 2 + 0];
                float v1 = acc[mt][nt][rr * 2 + 1];
                if (mode == 1)      { v0 += E[c]; v1 += E[c + 1]; }
                else if (mode == 2) { v0 += C[base + c]; v1 += C[base + c + 1]; }
                float2 o; o.x = v0; o.y = v1;
                *(float2*)&C[base + c] = o;
            }
        }
    }
}

// ---------------- embedding assembly ----------------
__device__ __forceinline__ float4 f4add(float4 a, float4 b) {
    a.x += b.x; a.y += b.y; a.z += b.z; a.w += b.w; return a;
}

__global__ void embed_k(const float* __restrict__ gf, const float* __restrict__ sos,
                        const float* __restrict__ nodee, const float* __restrict__ typee,
                        const float* __restrict__ pose, const int* __restrict__ sub)
{
    const int row = blockIdx.x;
    const int b = row / SS, s = row % SS;
    const int t = threadIdx.x;
    const int D4 = DD / 4;

    float4 acc = ((const float4*)pose)[(size_t)s * D4 + t];
    if (s == 0) {
        acc = f4add(acc, ((const float4*)gf)[(size_t)b * D4 + t]);
        acc = f4add(acc, ((const float4*)typee)[D4 + t]);
    } else {
        float4 bv, ne;
        if (s == 1) {
            bv = ((const float4*)sos)[t];
            ne = ((const float4*)nodee)[t];
        } else {
            const int tok = b * LL + (s - 2);
            bv = ((const float4*)g_x)[(size_t)tok * D4 + t];
            ne = ((const float4*)nodee)[(size_t)sub[tok] * D4 + t];
        }
        acc = f4add(acc, bv);
        acc = f4add(acc, ne);
        acc = f4add(acc, ((const float4*)typee)[t]);
    }
    ((float4*)g_h)[(size_t)row * D4 + t] = acc;
}

// ---------------- RMSNorm ----------------
__global__ void rmsnorm_k(const float* __restrict__ in, const float* __restrict__ w,
                          float* __restrict__ out)
{
    const int row = blockIdx.x;
    const int t = threadIdx.x;
    float4 v = ((const float4*)(in + (size_t)row * DD))[t];
    float ss = v.x * v.x + v.y * v.y + v.z * v.z + v.w * v.w;
    #pragma unroll
    for (int off = 16; off > 0; off >>= 1) ss += __shfl_xor_sync(0xffffffffu, ss, off);
    __shared__ float ws[8];
    if ((t & 31) == 0) ws[t >> 5] = ss;
    __syncthreads();
    float tot = ws[0] + ws[1] + ws[2] + ws[3] + ws[4] + ws[5] + ws[6] + ws[7];
    const float r = rsqrtf(tot * (1.0f / DD) + 1e-6f);
    float4 wv = ((const float4*)w)[t];
    float4 o;
    o.x = v.x * r * wv.x; o.y = v.y * r * wv.y;
    o.z = v.z * r * wv.z; o.w = v.w * r * wv.w;
    ((float4*)(out + (size_t)row * DD))[t] = o;
}

// ---------------- fused attention (flash-style, fp32) ----------------
#define ATT_P 65
#define ATT_SMEM_FLOATS (4 * 64 * ATT_P + 3 * 64)

__global__ void __launch_bounds__(256)
attn_k(const int* __restrict__ spd, const float* __restrict__ spde,
       const int* __restrict__ tmlp)
{
    extern __shared__ float smd[];
    float* Qs   = smd;
    float* Ks   = Qs + 64 * ATT_P;
    float* Vs   = Ks + 64 * ATT_P;
    float* St   = Vs + 64 * ATT_P;
    float* rowm = St + 64 * ATT_P;
    float* rowl = rowm + 64;
    float* rowc = rowl + 64;
    __shared__ float sc[32];

    const int tid = threadIdx.x;
    const int qt = blockIdx.x, h = blockIdx.y, b = blockIdx.z;
    const int q0 = qt * 64;
    int nq = SS - q0; if (nq > 64) nq = 64;
    const int limit = tmlp[b] + 2;

    if (tid < 32) sc[tid] = spde[tid * HH + h];
    if (tid < 64) { rowm[tid] = -1e30f; rowl[tid] = 0.f; rowc[tid] = 1.f; }

    const float* qb = g_qkv + ((size_t)(b * SS + q0)) * DD + h * 64;
    #pragma unroll
    for (int r = 0; r < 16; r++) {
        const int idx = tid + r * 256;
        const int qi = idx >> 6, d = idx & 63;
        Qs[d * ATT_P + qi] = (qi < nq) ? qb[(size_t)qi * DD + d] : 0.f;
    }

    const int ty = tid >> 4, tx = tid & 15;
    const int i0 = ty << 2, j0 = tx << 2;

    float oacc[4][4];
    #pragma unroll
    for (int a = 0; a < 4; a++)
        #pragma unroll
        for (int c = 0; c < 4; c++) oacc[a][c] = 0.f;

    for (int kt = 0; kt < (SS + 63) / 64; kt++) {
        const int k0 = kt * 64;
        int nk = SS - k0; if (nk > 64) nk = 64;
        __syncthreads();

        const float* kb = g_qkv + QKV_OFF   + ((size_t)(b * SS + k0)) * DD + h * 64;
        const float* vb = g_qkv + 2*QKV_OFF + ((size_t)(b * SS + k0)) * DD + h * 64;
        #pragma unroll
        for (int r = 0; r < 16; r++) {
            const int idx = tid + r * 256;
            const int j = idx >> 6, d = idx & 63;
            const bool ok = (j < nk);
            Ks[d * ATT_P + j] = ok ? kb[(size_t)j * DD + d] : 0.f;
            Vs[j * ATT_P + d] = ok ? vb[(size_t)j * DD + d] : 0.f;
        }
        __syncthreads();

        float sacc[4][4];
        #pragma unroll
        for (int a = 0; a < 4; a++)
            #pragma unroll
            for (int c = 0; c < 4; c++) sacc[a][c] = 0.f;

        #pragma unroll 4
        for (int d = 0; d < 64; d++) {
            float qv0 = Qs[d * ATT_P + i0 + 0];
            float qv1 = Qs[d * ATT_P + i0 + 1];
            float qv2 = Qs[d * ATT_P + i0 + 2];
            float qv3 = Qs[d * ATT_P + i0 + 3];
            float kv0 = Ks[d * ATT_P + j0 + 0];
            float kv1 = Ks[d * ATT_P + j0 + 1];
            float kv2 = Ks[d * ATT_P + j0 + 2];
            float kv3 = Ks[d * ATT_P + j0 + 3];
            sacc[0][0] += qv0 * kv0; sacc[0][1] += qv0 * kv1; sacc[0][2] += qv0 * kv2; sacc[0][3] += qv0 * kv3;
            sacc[1][0] += qv1 * kv0; sacc[1][1] += qv1 * kv1; sacc[1][2] += qv1 * kv2; sacc[1][3] += qv1 * kv3;
            sacc[2][0] += qv2 * kv0; sacc[2][1] += qv2 * kv1; sacc[2][2] += qv2 * kv2; sacc[2][3] += qv2 * kv3;
            sacc[3][0] += qv3 * kv0; sacc[3][1] += qv3 * kv1; sacc[3][2] += qv3 * kv2; sacc[3][3] += qv3 * kv3;
        }

        #pragma unroll
        for (int ii = 0; ii < 4; ii++) {
            const int qi = i0 + ii;
            const int qg = q0 + qi;
            const bool qok = (qg < SS);
            const bool qmask = qok && (qg >= limit);
            #pragma unroll
            for (int jj = 0; jj < 4; jj++) {
                const int jl = j0 + jj;
                const int kg = k0 + jl;
                float o;
                if (!qok || jl >= nk) o = -1e30f;
                else if (qmask) o = 0.f;     // ref's fp32 flush -> uniform softmax
                else {
                    int id;
                    if (qg >= 2 && kg >= 2)
                        id = spd[((size_t)b * LL + (qg - 2)) * LL + (kg - 2)];
                    else
                        id = (qg == kg) ? 0 : 31;
                    o = sacc[ii][jj] * 0.125f + sc[id];
                }
                St[jl * ATT_P + qi] = o;
            }
        }
        __syncthreads();

        if (tid < nq) {
            const int i = tid;
            float mt = rowm[i];
            #pragma unroll 8
            for (int j = 0; j < 64; j++) mt = fmaxf(mt, St[j * ATT_P + i]);
            const float corr = __expf(rowm[i] - mt);
            float ls = 0.f;
            #pragma unroll 8
            for (int j = 0; j < 64; j++) {
                const float p = __expf(St[j * ATT_P + i] - mt);
                St[j * ATT_P + i] = p;
                ls += p;
            }
            rowl[i] = rowl[i] * corr + ls;
            rowm[i] = mt;
            rowc[i] = corr;
        }
        __syncthreads();

        float cr0 = rowc[i0 + 0], cr1 = rowc[i0 + 1], cr2 = rowc[i0 + 2], cr3 = rowc[i0 + 3];
        #pragma unroll
        for (int c = 0; c < 4; c++) {
            oacc[0][c] *= cr0; oacc[1][c] *= cr1; oacc[2][c] *= cr2; oacc[3][c] *= cr3;
        }
        #pragma unroll 4
        for (int j = 0; j < 64; j++) {
            float p0 = St[j * ATT_P + i0 + 0];
            float p1 = St[j * ATT_P + i0 + 1];
            float p2 = St[j * ATT_P + i0 + 2];
            float p3 = St[j * ATT_P + i0 + 3];
            float v0 = Vs[j * ATT_P + j0 + 0];
            float v1 = Vs[j * ATT_P + j0 + 1];
            float v2 = Vs[j * ATT_P + j0 + 2];
            float v3 = Vs[j * ATT_P + j0 + 3];
            oacc[0][0] += p0 * v0; oacc[0][1] += p0 * v1; oacc[0][2] += p0 * v2; oacc[0][3] += p0 * v3;
            oacc[1][0] += p1 * v0; oacc[1][1] += p1 * v1; oacc[1][2] += p1 * v2; oacc[1][3] += p1 * v3;
            oacc[2][0] += p2 * v0; oacc[2][1] += p2 * v1; oacc[2][2] += p2 * v2; oacc[2][3] += p2 * v3;
            oacc[3][0] += p3 * v0; oacc[3][1] += p3 * v1; oacc[3][2] += p3 * v2; oacc[3][3] += p3 * v3;
        }
    }

    #pragma unroll
    for (int ii = 0; ii < 4; ii++) {
        const int qi = i0 + ii;
        if (qi < nq) {
            const int qg = q0 + qi;
            const float inv = 1.f / rowl[qi];
            float* ob = g_att + ((size_t)(b * SS + qg)) * DD + h * 64 + j0;
            #pragma unroll
            for (int jj = 0; jj < 4; jj++) ob[jj] = oacc[ii][jj] * inv;
        }
    }
}

// ---------------- host driver ----------------
extern "C" void kernel_launch(void* const* d_in, const int* in_sizes, int n_in,
                              void* d_out, int out_size)
{
    const float* graph   = (const float*)d_in[0];
    const float* infeat  = (const float*)d_in[1];
    const float* projW   = (const float*)d_in[2];
    const float* projb   = (const float*)d_in[3];
    const float* sos     = (const float*)d_in[4];
    const float* nodee   = (const float*)d_in[5];
    const float* typee   = (const float*)d_in[6];
    const float* pose    = (const float*)d_in[7];
    const float* spde    = (const float*)d_in[8];
    const float* anorm   = (const float*)d_in[9];
    const float* wq      = (const float*)d_in[10];
    const float* wk      = (const float*)d_in[11];
    const float* wv      = (const float*)d_in[12];
    const float* wo      = (const float*)d_in[13];
    const float* fnorm   = (const float*)d_in[14];
    const float* w1      = (const float*)d_in[15];
    const float* w2      = (const float*)d_in[16];
    const float* w3      = (const float*)d_in[17];
    const float* finaln  = (const float*)d_in[18];
    const float* outW    = (const float*)d_in[19];
    const float* outb    = (const float*)d_in[20];
    const int*   sub     = (const int*)d_in[21];
    const int*   tml     = (const int*)d_in[22];
    const int*   spdidx  = (const int*)d_in[23];
    (void)in_sizes; (void)n_in; (void)out_size;

    float *ph, *px, *pqkv, *patt, *pffn;
    cudaGetSymbolAddress((void**)&ph,   g_h);
    cudaGetSymbolAddress((void**)&px,   g_x);
    cudaGetSymbolAddress((void**)&pqkv, g_qkv);
    cudaGetSymbolAddress((void**)&patt, g_att);
    cudaGetSymbolAddress((void**)&pffn, g_ffn);
    float* pq = pqkv;
    float* pk = pqkv + QKV_OFF;
    float* pv = pqkv + 2*QKV_OFF;
    float* pf0 = pffn;
    float* pf1 = pffn + FFN_OFF;

    const int attSmem = ATT_SMEM_FLOATS * (int)sizeof(float);
    cudaFuncSetAttribute(attn_k, cudaFuncAttributeMaxDynamicSharedMemorySize, attSmem);

    // z=1 variant
    auto gemm1 = [](const float* A, const float* A2, const float* W, float* C,
                    const float* E, int M, int N, int K, int mode, int aop) {
        dim3 g((N + 127) / 128, (M + 127) / 128, 1);
        gemm_tc<<<g, 256>>>(A, A2, W, nullptr, nullptr, C, nullptr, nullptr,
                            E, M, N, K, mode, aop);
    };

    // proj (bias fused) into g_x, then embeddings into g_h
    gemm1(infeat, infeat, projW, px, projb, BB * LL, DD, FDIM, 1, 0);
    embed_k<<<MROWS, 256>>>(graph, sos, nodee, typee, pose, sub);

    for (int i = 0; i < NLAYER; i++) {
        const size_t wOff = (size_t)i * DD * DD;
        const size_t fOff = (size_t)i * DD * DFF;

        rmsnorm_k<<<MROWS, 256>>>(ph, anorm + (size_t)i * DD, px);

        // fused QKV: grid.z = 3
        {
            dim3 g((DD + 127) / 128, (MROWS + 127) / 128, 3);
            gemm_tc<<<g, 256>>>(px, px, wq + wOff, wk + wOff, wv + wOff,
                                pq, pk, pv, nullptr, MROWS, DD, DD, 0, 0);
        }

        attn_k<<<dim3((SS + 63) / 64, HH, BB), 256, attSmem>>>(spdidx, spde, tml);

        gemm1(patt, patt, wo + wOff, ph, nullptr, MROWS, DD, DD, 2, 0);   // h += att @ wo

        rmsnorm_k<<<MROWS, 256>>>(ph, fnorm + (size_t)i * DD, px);

        // fused w1/w3: grid.z = 2
        {
            dim3 g((DFF + 127) / 128, (MROWS + 127) / 128, 2);
            gemm_tc<<<g, 256>>>(px, px, w1 + fOff, w3 + fOff, nullptr,
                                pf0, pf1, nullptr, nullptr, MROWS, DFF, DD, 0, 0);
        }
        // h += (silu(f0) * f1) @ w2 — silu*mul fused into A-load
        gemm1(pf0, pf1, w2 + (size_t)i * DFF * DD, ph, nullptr, MROWS, DD, DFF, 2, 2);
    }

    rmsnorm_k<<<MROWS, 256>>>(ph, finaln, px);
    // logits: skip graph row via remap (aop=1); bias fused
    gemm1(px, px, outW, (float*)d_out, outb, OUTROWS, NVOC, DD, 1, 1);
}

// round 12
// speedup vs baseline: 1.7657x; 1.7657x over previous
#include <cuda_runtime.h>
#include <cuda_bf16.h>
#include <math.h>

// ---------------- problem constants ----------------
#define BB     2
#define LL     1024
#define DD     1024
#define HH     16
#define FDIM   512
#define NLAYER 4
#define NVOC   5000
#define DFF    4096
#define SS     1026            // seqlen = 1 (graph) + 1 (sos) + L
#define MROWS  (BB*SS)         // 2052
#define OUTROWS (BB*(SS-1))    // 2050 output rows (skip graph row)

#define QKV_OFF (BB*SS*DD)
#define FFN_OFF (BB*SS*DFF)

// ---------------- scratch (device globals; no allocation allowed) ----------------
__device__ float g_h  [BB*SS*DD];
__device__ float g_x  [BB*SS*DD];
__device__ float g_qkv[3*BB*SS*DD];
__device__ float g_att[BB*SS*DD];
__device__ float g_ffn[2*BB*SS*DFF];

// ---------------- tf32 helpers ----------------
__device__ __forceinline__ unsigned tf32cvt(float x) {
    unsigned r;
    asm("cvt.rna.tf32.f32 %0, %1;" : "=r"(r) : "f"(x));
    return r;
}
__device__ __forceinline__ void mma_tf32(float* d, const unsigned* a, const unsigned* b) {
    asm volatile(
        "mma.sync.aligned.m16n8k8.row.col.f32.tf32.tf32.f32 "
        "{%0,%1,%2,%3}, {%4,%5,%6,%7}, {%8,%9}, {%0,%1,%2,%3};"
        : "+f"(d[0]), "+f"(d[1]), "+f"(d[2]), "+f"(d[3])
        : "r"(a[0]), "r"(a[1]), "r"(a[2]), "r"(a[3]), "r"(b[0]), "r"(b[1]));
}
__device__ __forceinline__ void ldsm4(unsigned* f, unsigned saddr) {
    asm volatile("ldmatrix.sync.aligned.m8n8.x4.shared.b16 {%0,%1,%2,%3}, [%4];"
        : "=r"(f[0]), "=r"(f[1]), "=r"(f[2]), "=r"(f[3]) : "r"(saddr));
}

// ---------------- TF32 tensor-core GEMM ----------------
// C[M,N] (op) A[M,K] @ W[K,N], K % 16 == 0, N % 4 == 0.
// mode 0: C = A@W
// mode 1: C = A@W + E   (E = bias vector, length N)
// mode 2: C = C + A@W   (residual)
// mode 3: C = silu(E[m,n]) * (A@W)  (E = matrix, same layout as C)
// arm  1: A row remap for logits: arow = (m/1025)*SS + 1 + m%1025
#define AST 20    // As row stride in tf32 (80B: LDSM rows hit all 8 bank-quads)
#define BST 136   // Bs row stride (scalar LDS conflict-free)

__global__ void __launch_bounds__(256, 2)
gemm_tc(const float* __restrict__ A, const float* __restrict__ W,
        float* __restrict__ C, const float* __restrict__ E,
        int M, int N, int K, int mode, int arm)
{
    __shared__ unsigned As[2][128][AST];
    __shared__ unsigned Bs[2][16][BST];

    const int tid = threadIdx.x;
    const int bm = blockIdx.y * 128;
    const int bn = blockIdx.x * 128;

    // ---- gmem load indices (2 float4 per thread per matrix) ----
    const int a_r0 = tid >> 2;            // 0..63
    const int a_c  = (tid & 3) << 2;      // k offset 0/4/8/12
    const int b_k0 = tid >> 5;            // 0..7
    const int b_c  = (tid & 31) << 2;

    int am0 = bm + a_r0, am1 = bm + a_r0 + 64;
    const bool av0 = am0 < M, av1 = am1 < M;
    if (arm == 1) {
        if (av0) am0 = (am0 / 1025) * SS + 1 + (am0 % 1025);
        if (av1) am1 = (am1 / 1025) * SS + 1 + (am1 % 1025);
    }
    const float* ap0 = A + (size_t)am0 * K + a_c;
    const float* ap1 = A + (size_t)am1 * K + a_c;
    const float* bp0 = W + (size_t)b_k0 * N + bn + b_c;
    const float* bp1 = W + (size_t)(b_k0 + 8) * N + bn + b_c;
    const bool bv = (bn + b_c) < N;

    // ---- warp / fragment indices ----
    const int wid = tid >> 5, lane = tid & 31;
    const int wm = (wid >> 2) * 64;       // warp row base
    const int wn = (wid & 3) * 32;        // warp col base
    const int lm = lane >> 2;             // 0..7
    const int lk = lane & 3;              // 0..3

    // LDSM source mapping (verified bit-identical vs scalar LDS in R9)
    const int lds_row  = (lane & 7) + ((lane >> 3) & 1) * 8;
    const int lds_bcol = ((lane >> 4) & 1) * 16;    // +16B = +4 tf32 cols
    const unsigned asBase0 = (unsigned)__cvta_generic_to_shared(&As[0][0][0]);
    const unsigned asBase1 = (unsigned)__cvta_generic_to_shared(&As[1][0][0]);

    float acc[4][4][4];
    #pragma unroll
    for (int i = 0; i < 4; i++)
        #pragma unroll
        for (int j = 0; j < 4; j++)
            #pragma unroll
            for (int r = 0; r < 4; r++) acc[i][j][r] = 0.f;

    const int nkt = K >> 4;
    float4 a4_0, a4_1, b4_0, b4_1;

    // preload tile 0
    a4_0 = av0 ? *(const float4*)ap0 : make_float4(0.f,0.f,0.f,0.f);
    a4_1 = av1 ? *(const float4*)ap1 : make_float4(0.f,0.f,0.f,0.f);
    b4_0 = bv  ? *(const float4*)bp0 : make_float4(0.f,0.f,0.f,0.f);
    b4_1 = bv  ? *(const float4*)bp1 : make_float4(0.f,0.f,0.f,0.f);

    int buf = 0;
    {
        uint4 ua0 = { tf32cvt(a4_0.x), tf32cvt(a4_0.y), tf32cvt(a4_0.z), tf32cvt(a4_0.w) };
        uint4 ua1 = { tf32cvt(a4_1.x), tf32cvt(a4_1.y), tf32cvt(a4_1.z), tf32cvt(a4_1.w) };
        uint4 ub0 = { tf32cvt(b4_0.x), tf32cvt(b4_0.y), tf32cvt(b4_0.z), tf32cvt(b4_0.w) };
        uint4 ub1 = { tf32cvt(b4_1.x), tf32cvt(b4_1.y), tf32cvt(b4_1.z), tf32cvt(b4_1.w) };
        *(uint4*)&As[0][a_r0     ][a_c] = ua0;
        *(uint4*)&As[0][a_r0 + 64][a_c] = ua1;
        *(uint4*)&Bs[0][b_k0     ][b_c] = ub0;
        *(uint4*)&Bs[0][b_k0 + 8 ][b_c] = ub1;
    }
    __syncthreads();

    for (int kt = 0; kt < nkt; kt++) {
        if (kt + 1 < nkt) {
            ap0 += 16; ap1 += 16;
            bp0 += (size_t)16 * N; bp1 += (size_t)16 * N;
            a4_0 = av0 ? *(const float4*)ap0 : make_float4(0.f,0.f,0.f,0.f);
            a4_1 = av1 ? *(const float4*)ap1 : make_float4(0.f,0.f,0.f,0.f);
            b4_0 = bv  ? *(const float4*)bp0 : make_float4(0.f,0.f,0.f,0.f);
            b4_1 = bv  ? *(const float4*)bp1 : make_float4(0.f,0.f,0.f,0.f);
        }

        const unsigned asb = buf ? asBase1 : asBase0;
        #pragma unroll
        for (int ks = 0; ks < 2; ks++) {
            const int kb = ks * 8;
            unsigned af[4][4], bf[4][2];
            #pragma unroll
            for (int mt = 0; mt < 4; mt++) {
                const int r = wm + mt * 16 + lds_row;
                ldsm4(af[mt], asb + (unsigned)(r * (AST*4) + kb * 4 + lds_bcol));
            }
            #pragma unroll
            for (int nt = 0; nt < 4; nt++) {
                const int c = wn + nt * 8 + lm;
                bf[nt][0] = Bs[buf][kb + lk    ][c];
                bf[nt][1] = Bs[buf][kb + lk + 4][c];
            }
            #pragma unroll
            for (int mt = 0; mt < 4; mt++)
                #pragma unroll
                for (int nt = 0; nt < 4; nt++)
                    mma_tf32(acc[mt][nt], af[mt], bf[nt]);
        }

        if (kt + 1 < nkt) {
            const int nb = buf ^ 1;
            uint4 ua0 = { tf32cvt(a4_0.x), tf32cvt(a4_0.y), tf32cvt(a4_0.z), tf32cvt(a4_0.w) };
            uint4 ua1 = { tf32cvt(a4_1.x), tf32cvt(a4_1.y), tf32cvt(a4_1.z), tf32cvt(a4_1.w) };
            uint4 ub0 = { tf32cvt(b4_0.x), tf32cvt(b4_0.y), tf32cvt(b4_0.z), tf32cvt(b4_0.w) };
            uint4 ub1 = { tf32cvt(b4_1.x), tf32cvt(b4_1.y), tf32cvt(b4_1.z), tf32cvt(b4_1.w) };
            *(uint4*)&As[nb][a_r0     ][a_c] = ua0;
            *(uint4*)&As[nb][a_r0 + 64][a_c] = ua1;
            *(uint4*)&Bs[nb][b_k0     ][b_c] = ub0;
            *(uint4*)&Bs[nb][b_k0 + 8 ][b_c] = ub1;
        }
        __syncthreads();
        buf ^= 1;
    }

    // ---- epilogue ----
    #pragma unroll
    for (int mt = 0; mt < 4; mt++) {
        #pragma unroll
        for (int rr = 0; rr < 2; rr++) {
            const int m = bm + wm + mt * 16 + lm + rr * 8;
            if (m >= M) continue;
            const size_t base = (size_t)m * N;
            #pragma unroll
            for (int nt = 0; nt < 4; nt++) {
                const int c = bn + wn + nt * 8 + 2 * lk;
                if (c >= N) continue;
                float v0 = acc[mt][nt][rr * 2 + 0];
                float v1 = acc[mt][nt][rr * 2 + 1];
                if (mode == 1)      { v0 += E[c]; v1 += E[c + 1]; }
                else if (mode == 2) { v0 += C[base + c]; v1 += C[base + c + 1]; }
                else if (mode == 3) {
                    float t0 = E[base + c], t1 = E[base + c + 1];
                    v0 *= t0 / (1.f + __expf(-t0));
                    v1 *= t1 / (1.f + __expf(-t1));
                }
                float2 o; o.x = v0; o.y = v1;
                *(float2*)&C[base + c] = o;
            }
        }
    }
}

// ---------------- embedding assembly ----------------
__device__ __forceinline__ float4 f4add(float4 a, float4 b) {
    a.x += b.x; a.y += b.y; a.z += b.z; a.w += b.w; return a;
}

__global__ void embed_k(const float* __restrict__ gf, const float* __restrict__ sos,
                        const float* __restrict__ nodee, const float* __restrict__ typee,
                        const float* __restrict__ pose, const int* __restrict__ sub)
{
    const int row = blockIdx.x;
    const int b = row / SS, s = row % SS;
    const int t = threadIdx.x;
    const int D4 = DD / 4;

    float4 acc = ((const float4*)pose)[(size_t)s * D4 + t];
    if (s == 0) {
        acc = f4add(acc, ((const float4*)gf)[(size_t)b * D4 + t]);
        acc = f4add(acc, ((const float4*)typee)[D4 + t]);
    } else {
        float4 bv, ne;
        if (s == 1) {
            bv = ((const float4*)sos)[t];
            ne = ((const float4*)nodee)[t];
        } else {
            const int tok = b * LL + (s - 2);
            bv = ((const float4*)g_x)[(size_t)tok * D4 + t];
            ne = ((const float4*)nodee)[(size_t)sub[tok] * D4 + t];
        }
        acc = f4add(acc, bv);
        acc = f4add(acc, ne);
        acc = f4add(acc, ((const float4*)typee)[t]);
    }
    ((float4*)g_h)[(size_t)row * D4 + t] = acc;
}

// ---------------- RMSNorm ----------------
__global__ void rmsnorm_k(const float* __restrict__ in, const float* __restrict__ w,
                          float* __restrict__ out)
{
    const int row = blockIdx.x;
    const int t = threadIdx.x;
    float4 v = ((const float4*)(in + (size_t)row * DD))[t];
    float ss = v.x * v.x + v.y * v.y + v.z * v.z + v.w * v.w;
    #pragma unroll
    for (int off = 16; off > 0; off >>= 1) ss += __shfl_xor_sync(0xffffffffu, ss, off);
    __shared__ float ws[8];
    if ((t & 31) == 0) ws[t >> 5] = ss;
    __syncthreads();
    float tot = ws[0] + ws[1] + ws[2] + ws[3] + ws[4] + ws[5] + ws[6] + ws[7];
    const float r = rsqrtf(tot * (1.0f / DD) + 1e-6f);
    float4 wv = ((const float4*)w)[t];
    float4 o;
    o.x = v.x * r * wv.x; o.y = v.y * r * wv.y;
    o.z = v.z * r * wv.z; o.w = v.w * r * wv.w;
    ((float4*)(out + (size_t)row * DD))[t] = o;
}

// ---------------- fused attention (flash-style, fp32) ----------------
#define ATT_P 65
#define ATT_SMEM_FLOATS (4 * 64 * ATT_P + 3 * 64)

__global__ void __launch_bounds__(256)
attn_k(const int* __restrict__ spd, const float* __restrict__ spde,
       const int* __restrict__ tmlp)
{
    extern __shared__ float smd[];
    float* Qs   = smd;
    float* Ks   = Qs + 64 * ATT_P;
    float* Vs   = Ks + 64 * ATT_P;
    float* St   = Vs + 64 * ATT_P;
    float* rowm = St + 64 * ATT_P;
    float* rowl = rowm + 64;
    float* rowc = rowl + 64;
    __shared__ float sc[32];

    const int tid = threadIdx.x;
    const int qt = blockIdx.x, h = blockIdx.y, b = blockIdx.z;
    const int q0 = qt * 64;
    int nq = SS - q0; if (nq > 64) nq = 64;
    const int limit = tmlp[b] + 2;

    if (tid < 32) sc[tid] = spde[tid * HH + h];
    if (tid < 64) { rowm[tid] = -1e30f; rowl[tid] = 0.f; rowc[tid] = 1.f; }

    const float* qb = g_qkv + ((size_t)(b * SS + q0)) * DD + h * 64;
    #pragma unroll
    for (int r = 0; r < 16; r++) {
        const int idx = tid + r * 256;
        const int qi = idx >> 6, d = idx & 63;
        Qs[d * ATT_P + qi] = (qi < nq) ? qb[(size_t)qi * DD + d] : 0.f;
    }

    const int ty = tid >> 4, tx = tid & 15;
    const int i0 = ty << 2, j0 = tx << 2;

    float oacc[4][4];
    #pragma unroll
    for (int a = 0; a < 4; a++)
        #pragma unroll
        for (int c = 0; c < 4; c++) oacc[a][c] = 0.f;

    for (int kt = 0; kt < (SS + 63) / 64; kt++) {
        const int k0 = kt * 64;
        int nk = SS - k0; if (nk > 64) nk = 64;
        __syncthreads();

        const float* kb = g_qkv + QKV_OFF   + ((size_t)(b * SS + k0)) * DD + h * 64;
        const float* vb = g_qkv + 2*QKV_OFF + ((size_t)(b * SS + k0)) * DD + h * 64;
        #pragma unroll
        for (int r = 0; r < 16; r++) {
            const int idx = tid + r * 256;
            const int j = idx >> 6, d = idx & 63;
            const bool ok = (j < nk);
            Ks[d * ATT_P + j] = ok ? kb[(size_t)j * DD + d] : 0.f;
            Vs[j * ATT_P + d] = ok ? vb[(size_t)j * DD + d] : 0.f;
        }
        __syncthreads();

        float sacc[4][4];
        #pragma unroll
        for (int a = 0; a < 4; a++)
            #pragma unroll
            for (int c = 0; c < 4; c++) sacc[a][c] = 0.f;

        #pragma unroll 4
        for (int d = 0; d < 64; d++) {
            float qv0 = Qs[d * ATT_P + i0 + 0];
            float qv1 = Qs[d * ATT_P + i0 + 1];
            float qv2 = Qs[d * ATT_P + i0 + 2];
            float qv3 = Qs[d * ATT_P + i0 + 3];
            float kv0 = Ks[d * ATT_P + j0 + 0];
            float kv1 = Ks[d * ATT_P + j0 + 1];
            float kv2 = Ks[d * ATT_P + j0 + 2];
            float kv3 = Ks[d * ATT_P + j0 + 3];
            sacc[0][0] += qv0 * kv0; sacc[0][1] += qv0 * kv1; sacc[0][2] += qv0 * kv2; sacc[0][3] += qv0 * kv3;
            sacc[1][0] += qv1 * kv0; sacc[1][1] += qv1 * kv1; sacc[1][2] += qv1 * kv2; sacc[1][3] += qv1 * kv3;
            sacc[2][0] += qv2 * kv0; sacc[2][1] += qv2 * kv1; sacc[2][2] += qv2 * kv2; sacc[2][3] += qv2 * kv3;
            sacc[3][0] += qv3 * kv0; sacc[3][1] += qv3 * kv1; sacc[3][2] += qv3 * kv2; sacc[3][3] += qv3 * kv3;
        }

        #pragma unroll
        for (int ii = 0; ii < 4; ii++) {
            const int qi = i0 + ii;
            const int qg = q0 + qi;
            const bool qok = (qg < SS);
            const bool qmask = qok && (qg >= limit);
            #pragma unroll
            for (int jj = 0; jj < 4; jj++) {
                const int jl = j0 + jj;
                const int kg = k0 + jl;
                float o;
                if (!qok || jl >= nk) o = -1e30f;
                else if (qmask) o = 0.f;     // ref's fp32 flush -> uniform softmax
                else {
                    int id;
                    if (qg >= 2 && kg >= 2)
                        id = spd[((size_t)b * LL + (qg - 2)) * LL + (kg - 2)];
                    else
                        id = (qg == kg) ? 0 : 31;
                    o = sacc[ii][jj] * 0.125f + sc[id];
                }
                St[jl * ATT_P + qi] = o;
            }
        }
        __syncthreads();

        if (tid < nq) {
            const int i = tid;
            float mt = rowm[i];
            #pragma unroll 8
            for (int j = 0; j < 64; j++) mt = fmaxf(mt, St[j * ATT_P + i]);
            const float corr = __expf(rowm[i] - mt);
            float ls = 0.f;
            #pragma unroll 8
            for (int j = 0; j < 64; j++) {
                const float p = __expf(St[j * ATT_P + i] - mt);
                St[j * ATT_P + i] = p;
                ls += p;
            }
            rowl[i] = rowl[i] * corr + ls;
            rowm[i] = mt;
            rowc[i] = corr;
        }
        __syncthreads();

        float cr0 = rowc[i0 + 0], cr1 = rowc[i0 + 1], cr2 = rowc[i0 + 2], cr3 = rowc[i0 + 3];
        #pragma unroll
        for (int c = 0; c < 4; c++) {
            oacc[0][c] *= cr0; oacc[1][c] *= cr1; oacc[2][c] *= cr2; oacc[3][c] *= cr3;
        }
        #pragma unroll 4
        for (int j = 0; j < 64; j++) {
            float p0 = St[j * ATT_P + i0 + 0];
            float p1 = St[j * ATT_P + i0 + 1];
            float p2 = St[j * ATT_P + i0 + 2];
            float p3 = St[j * ATT_P + i0 + 3];
            float v0 = Vs[j * ATT_P + j0 + 0];
            float v1 = Vs[j * ATT_P + j0 + 1];
            float v2 = Vs[j * ATT_P + j0 + 2];
            float v3 = Vs[j * ATT_P + j0 + 3];
            oacc[0][0] += p0 * v0; oacc[0][1] += p0 * v1; oacc[0][2] += p0 * v2; oacc[0][3] += p0 * v3;
            oacc[1][0] += p1 * v0; oacc[1][1] += p1 * v1; oacc[1][2] += p1 * v2; oacc[1][3] += p1 * v3;
            oacc[2][0] += p2 * v0; oacc[2][1] += p2 * v1; oacc[2][2] += p2 * v2; oacc[2][3] += p2 * v3;
            oacc[3][0] += p3 * v0; oacc[3][1] += p3 * v1; oacc[3][2] += p3 * v2; oacc[3][3] += p3 * v3;
        }
    }

    #pragma unroll
    for (int ii = 0; ii < 4; ii++) {
        const int qi = i0 + ii;
        if (qi < nq) {
            const int qg = q0 + qi;
            const float inv = 1.f / rowl[qi];
            float* ob = g_att + ((size_t)(b * SS + qg)) * DD + h * 64 + j0;
            #pragma unroll
            for (int jj = 0; jj < 4; jj++) ob[jj] = oacc[ii][jj] * inv;
        }
    }
}

// ---------------- host driver ----------------
extern "C" void kernel_launch(void* const* d_in, const int* in_sizes, int n_in,
                              void* d_out, int out_size)
{
    const float* graph   = (const float*)d_in[0];
    const float* infeat  = (const float*)d_in[1];
    const float* projW   = (const float*)d_in[2];
    const float* projb   = (const float*)d_in[3];
    const float* sos     = (const float*)d_in[4];
    const float* nodee   = (const float*)d_in[5];
    const float* typee   = (const float*)d_in[6];
    const float* pose    = (const float*)d_in[7];
    const float* spde    = (const float*)d_in[8];
    const float* anorm   = (const float*)d_in[9];
    const float* wq      = (const float*)d_in[10];
    const float* wk      = (const float*)d_in[11];
    const float* wv      = (const float*)d_in[12];
    const float* wo      = (const float*)d_in[13];
    const float* fnorm   = (const float*)d_in[14];
    const float* w1      = (const float*)d_in[15];
    const float* w2      = (const float*)d_in[16];
    const float* w3      = (const float*)d_in[17];
    const float* finaln  = (const float*)d_in[18];
    const float* outW    = (const float*)d_in[19];
    const float* outb    = (const float*)d_in[20];
    const int*   sub     = (const int*)d_in[21];
    const int*   tml     = (const int*)d_in[22];
    const int*   spdidx  = (const int*)d_in[23];
    (void)in_sizes; (void)n_in; (void)out_size;

    float *ph, *px, *pqkv, *patt, *pffn;
    cudaGetSymbolAddress((void**)&ph,   g_h);
    cudaGetSymbolAddress((void**)&px,   g_x);
    cudaGetSymbolAddress((void**)&pqkv, g_qkv);
    cudaGetSymbolAddress((void**)&patt, g_att);
    cudaGetSymbolAddress((void**)&pffn, g_ffn);
    float* pq = pqkv;
    float* pk = pqkv + QKV_OFF;
    float* pv = pqkv + 2*QKV_OFF;
    float* pt1 = pffn;
    float* pt3 = pffn + FFN_OFF;

    const int attSmem = ATT_SMEM_FLOATS * (int)sizeof(float);
    cudaFuncSetAttribute(attn_k, cudaFuncAttributeMaxDynamicSharedMemorySize, attSmem);

    auto gemm = [](const float* A, const float* W, float* C, const float* E,
                   int M, int N, int K, int mode, int arm) {
        dim3 g((N + 127) / 128, (M + 127) / 128);
        gemm_tc<<<g, 256>>>(A, W, C, E, M, N, K, mode, arm);
    };

    // input projection (bias fused) into g_x, then embeddings into g_h
    gemm(infeat, projW, px, projb, BB * LL, DD, FDIM, 1, 0);
    embed_k<<<MROWS, 256>>>(graph, sos, nodee, typee, pose, sub);

    for (int i = 0; i < NLAYER; i++) {
        const size_t wOff = (size_t)i * DD * DD;
        const size_t fOff = (size_t)i * DD * DFF;

        rmsnorm_k<<<MROWS, 256>>>(ph, anorm + (size_t)i * DD, px);
        gemm(px, wq + wOff, pq, nullptr, MROWS, DD, DD, 0, 0);
        gemm(px, wk + wOff, pk, nullptr, MROWS, DD, DD, 0, 0);
        gemm(px, wv + wOff, pv, nullptr, MROWS, DD, DD, 0, 0);

        attn_k<<<dim3((SS + 63) / 64, HH, BB), 256, attSmem>>>(spdidx, spde, tml);

        gemm(patt, wo + wOff, ph, nullptr, MROWS, DD, DD, 2, 0);   // h += att @ wo

        rmsnorm_k<<<MROWS, 256>>>(ph, fnorm + (size_t)i * DD, px);
        gemm(px, w1 + fOff, pt1, nullptr, MROWS, DFF, DD, 0, 0);   // t1 = x @ w1
        gemm(px, w3 + fOff, pt3, pt1,     MROWS, DFF, DD, 3, 0);   // t3 = silu(t1) * (x @ w3)
        gemm(pt3, w2 + (size_t)i * DFF * DD, ph, nullptr, MROWS, DD, DFF, 2, 0); // h += t3 @ w2
    }

    rmsnorm_k<<<MROWS, 256>>>(ph, finaln, px);
    // logits: skip graph row via remap; bias fused
    gemm(px, outW, (float*)d_out, outb, OUTROWS, NVOC, DD, 1, 1);
}

// round 14
// speedup vs baseline: 2.0979x; 1.1881x over previous
#include <cuda_runtime.h>
#include <cuda_bf16.h>
#include <math.h>

// ---------------- problem constants ----------------
#define BB     2
#define LL     1024
#define DD     1024
#define HH     16
#define FDIM   512
#define NLAYER 4
#define NVOC   5000
#define DFF    4096
#define SS     1026            // seqlen = 1 (graph) + 1 (sos) + L
#define MROWS  (BB*SS)         // 2052
#define OUTROWS (BB*(SS-1))    // 2050 output rows (skip graph row)

#define QKV_OFF (BB*SS*DD)
#define FFN_OFF (BB*SS*DFF)

// ---------------- scratch (device globals; no allocation allowed) ----------------
__device__ float g_h  [BB*SS*DD];
__device__ float g_x  [BB*SS*DD];
__device__ float g_qkv[3*BB*SS*DD];
__device__ float g_att[BB*SS*DD];
__device__ float g_ffn[2*BB*SS*DFF];
__device__ float g_vmean[BB*HH*64];

// ---------------- tf32 helpers ----------------
__device__ __forceinline__ unsigned tf32cvt(float x) {
    unsigned r;
    asm("cvt.rna.tf32.f32 %0, %1;" : "=r"(r) : "f"(x));
    return r;
}
__device__ __forceinline__ void mma_tf32(float* d, const unsigned* a, const unsigned* b) {
    asm volatile(
        "mma.sync.aligned.m16n8k8.row.col.f32.tf32.tf32.f32 "
        "{%0,%1,%2,%3}, {%4,%5,%6,%7}, {%8,%9}, {%0,%1,%2,%3};"
        : "+f"(d[0]), "+f"(d[1]), "+f"(d[2]), "+f"(d[3])
        : "r"(a[0]), "r"(a[1]), "r"(a[2]), "r"(a[3]), "r"(b[0]), "r"(b[1]));
}
__device__ __forceinline__ void ldsm4(unsigned* f, unsigned saddr) {
    asm volatile("ldmatrix.sync.aligned.m8n8.x4.shared.b16 {%0,%1,%2,%3}, [%4];"
        : "=r"(f[0]), "=r"(f[1]), "=r"(f[2]), "=r"(f[3]) : "r"(saddr));
}

// ---------------- TF32 tensor-core GEMM ----------------
// C[M,N] (op) A[M,K] @ W[K,N], K % 16 == 0, N % 4 == 0.
// mode 0: C = A@W
// mode 1: C = A@W + E   (E = bias vector, length N)
// mode 2: C = C + A@W   (residual)
// mode 3: C = silu(E[m,n]) * (A@W)  (E = matrix, same layout as C)
// arm  1: A row remap for logits: arow = (m/1025)*SS + 1 + m%1025
// MF = m-fragments per warp: 4 -> BM=128, 2 -> BM=64 (small-grid occupancy)
#define AST 20    // As row stride in tf32 (80B: LDSM rows hit all 8 bank-quads)
#define BST 136   // Bs row stride (scalar LDS conflict-free)

template<int MF>
__global__ void __launch_bounds__(256, 2)
gemm_tc(const float* __restrict__ A, const float* __restrict__ W,
        float* __restrict__ C, const float* __restrict__ E,
        int M, int N, int K, int mode, int arm)
{
    __shared__ unsigned As[2][MF*32][AST];
    __shared__ unsigned Bs[2][16][BST];

    const int tid = threadIdx.x;
    const int bm = blockIdx.y * (MF * 32);
    const int bn = blockIdx.x * 128;

    // ---- gmem load indices ----
    const int a_r0 = tid >> 2;            // 0..63
    const int a_c  = (tid & 3) << 2;      // k offset 0/4/8/12
    const int b_k0 = tid >> 5;            // 0..7
    const int b_c  = (tid & 31) << 2;

    int am0 = bm + a_r0, am1 = bm + a_r0 + 64;
    const bool av0 = am0 < M;
    const bool av1 = (MF == 4) && (am1 < M);
    if (arm == 1) {
        if (av0) am0 = (am0 / 1025) * SS + 1 + (am0 % 1025);
        if (av1) am1 = (am1 / 1025) * SS + 1 + (am1 % 1025);
    }
    const float* ap0 = A + (size_t)am0 * K + a_c;
    const float* ap1 = A + (size_t)am1 * K + a_c;
    const float* bp0 = W + (size_t)b_k0 * N + bn + b_c;
    const float* bp1 = W + (size_t)(b_k0 + 8) * N + bn + b_c;
    const bool bv = (bn + b_c) < N;

    // ---- warp / fragment indices ----
    const int wid = tid >> 5, lane = tid & 31;
    const int wm = (wid >> 2) * (MF * 16); // warp row base
    const int wn = (wid & 3) * 32;         // warp col base
    const int lm = lane >> 2;              // 0..7
    const int lk = lane & 3;               // 0..3

    const int lds_row  = (lane & 7) + ((lane >> 3) & 1) * 8;
    const int lds_bcol = ((lane >> 4) & 1) * 16;
    const unsigned asBase0 = (unsigned)__cvta_generic_to_shared(&As[0][0][0]);
    const unsigned asBase1 = (unsigned)__cvta_generic_to_shared(&As[1][0][0]);

    float acc[MF][4][4];
    #pragma unroll
    for (int i = 0; i < MF; i++)
        #pragma unroll
        for (int j = 0; j < 4; j++)
            #pragma unroll
            for (int r = 0; r < 4; r++) acc[i][j][r] = 0.f;

    const int nkt = K >> 4;
    float4 a4_0, a4_1, b4_0, b4_1;

    a4_0 = av0 ? *(const float4*)ap0 : make_float4(0.f,0.f,0.f,0.f);
    if (MF == 4) a4_1 = av1 ? *(const float4*)ap1 : make_float4(0.f,0.f,0.f,0.f);
    b4_0 = bv  ? *(const float4*)bp0 : make_float4(0.f,0.f,0.f,0.f);
    b4_1 = bv  ? *(const float4*)bp1 : make_float4(0.f,0.f,0.f,0.f);

    int buf = 0;
    {
        uint4 ua0 = { tf32cvt(a4_0.x), tf32cvt(a4_0.y), tf32cvt(a4_0.z), tf32cvt(a4_0.w) };
        uint4 ub0 = { tf32cvt(b4_0.x), tf32cvt(b4_0.y), tf32cvt(b4_0.z), tf32cvt(b4_0.w) };
        uint4 ub1 = { tf32cvt(b4_1.x), tf32cvt(b4_1.y), tf32cvt(b4_1.z), tf32cvt(b4_1.w) };
        *(uint4*)&As[0][a_r0][a_c] = ua0;
        if (MF == 4) {
            uint4 ua1 = { tf32cvt(a4_1.x), tf32cvt(a4_1.y), tf32cvt(a4_1.z), tf32cvt(a4_1.w) };
            *(uint4*)&As[0][a_r0 + 64][a_c] = ua1;
        }
        *(uint4*)&Bs[0][b_k0    ][b_c] = ub0;
        *(uint4*)&Bs[0][b_k0 + 8][b_c] = ub1;
    }
    __syncthreads();

    for (int kt = 0; kt < nkt; kt++) {
        if (kt + 1 < nkt) {
            ap0 += 16; ap1 += 16;
            bp0 += (size_t)16 * N; bp1 += (size_t)16 * N;
            a4_0 = av0 ? *(const float4*)ap0 : make_float4(0.f,0.f,0.f,0.f);
            if (MF == 4) a4_1 = av1 ? *(const float4*)ap1 : make_float4(0.f,0.f,0.f,0.f);
            b4_0 = bv  ? *(const float4*)bp0 : make_float4(0.f,0.f,0.f,0.f);
            b4_1 = bv  ? *(const float4*)bp1 : make_float4(0.f,0.f,0.f,0.f);
        }

        const unsigned asb = buf ? asBase1 : asBase0;
        #pragma unroll
        for (int ks = 0; ks < 2; ks++) {
            const int kb = ks * 8;
            unsigned af[MF][4], bf[4][2];
            #pragma unroll
            for (int mt = 0; mt < MF; mt++) {
                const int r = wm + mt * 16 + lds_row;
                ldsm4(af[mt], asb + (unsigned)(r * (AST*4) + kb * 4 + lds_bcol));
            }
            #pragma unroll
            for (int nt = 0; nt < 4; nt++) {
                const int c = wn + nt * 8 + lm;
                bf[nt][0] = Bs[buf][kb + lk    ][c];
                bf[nt][1] = Bs[buf][kb + lk + 4][c];
            }
            #pragma unroll
            for (int mt = 0; mt < MF; mt++)
                #pragma unroll
                for (int nt = 0; nt < 4; nt++)
                    mma_tf32(acc[mt][nt], af[mt], bf[nt]);
        }

        if (kt + 1 < nkt) {
            const int nb = buf ^ 1;
            uint4 ua0 = { tf32cvt(a4_0.x), tf32cvt(a4_0.y), tf32cvt(a4_0.z), tf32cvt(a4_0.w) };
            uint4 ub0 = { tf32cvt(b4_0.x), tf32cvt(b4_0.y), tf32cvt(b4_0.z), tf32cvt(b4_0.w) };
            uint4 ub1 = { tf32cvt(b4_1.x), tf32cvt(b4_1.y), tf32cvt(b4_1.z), tf32cvt(b4_1.w) };
            *(uint4*)&As[nb][a_r0][a_c] = ua0;
            if (MF == 4) {
                uint4 ua1 = { tf32cvt(a4_1.x), tf32cvt(a4_1.y), tf32cvt(a4_1.z), tf32cvt(a4_1.w) };
                *(uint4*)&As[nb][a_r0 + 64][a_c] = ua1;
            }
            *(uint4*)&Bs[nb][b_k0    ][b_c] = ub0;
            *(uint4*)&Bs[nb][b_k0 + 8][b_c] = ub1;
        }
        __syncthreads();
        buf ^= 1;
    }

    // ---- epilogue ----
    #pragma unroll
    for (int mt = 0; mt < MF; mt++) {
        #pragma unroll
        for (int rr = 0; rr < 2; rr++) {
            const int m = bm + wm + mt * 16 + lm + rr * 8;
            if (m >= M) continue;
            const size_t base = (size_t)m * N;
            #pragma unroll
            for (int nt = 0; nt < 4; nt++) {
                const int c = bn + wn + nt * 8 + 2 * lk;
                if (c >= N) continue;
                float v0 = acc[mt][nt][rr * 2 + 0];
                float v1 = acc[mt][nt][rr * 2 + 1];
                if (mode == 1)      { v0 += E[c]; v1 += E[c + 1]; }
                else if (mode == 2) { v0 += C[base + c]; v1 += C[base + c + 1]; }
                else if (mode == 3) {
                    float t0 = E[base + c], t1 = E[base + c + 1];
                    v0 *= t0 / (1.f + __expf(-t0));
                    v1 *= t1 / (1.f + __expf(-t1));
                }
                float2 o; o.x = v0; o.y = v1;
                *(float2*)&C[base + c] = o;
            }
        }
    }
}

// ---------------- embedding assembly ----------------
__device__ __forceinline__ float4 f4add(float4 a, float4 b) {
    a.x += b.x; a.y += b.y; a.z += b.z; a.w += b.w; return a;
}

__global__ void embed_k(const float* __restrict__ gf, const float* __restrict__ sos,
                        const float* __restrict__ nodee, const float* __restrict__ typee,
                        const float* __restrict__ pose, const int* __restrict__ sub)
{
    const int row = blockIdx.x;
    const int b = row / SS, s = row % SS;
    const int t = threadIdx.x;
    const int D4 = DD / 4;

    float4 acc = ((const float4*)pose)[(size_t)s * D4 + t];
    if (s == 0) {
        acc = f4add(acc, ((const float4*)gf)[(size_t)b * D4 + t]);
        acc = f4add(acc, ((const float4*)typee)[D4 + t]);
    } else {
        float4 bv, ne;
        if (s == 1) {
            bv = ((const float4*)sos)[t];
            ne = ((const float4*)nodee)[t];
        } else {
            const int tok = b * LL + (s - 2);
            bv = ((const float4*)g_x)[(size_t)tok * D4 + t];
            ne = ((const float4*)nodee)[(size_t)sub[tok] * D4 + t];
        }
        acc = f4add(acc, bv);
        acc = f4add(acc, ne);
        acc = f4add(acc, ((const float4*)typee)[t]);
    }
    ((float4*)g_h)[(size_t)row * D4 + t] = acc;
}

// ---------------- RMSNorm ----------------
__global__ void rmsnorm_k(const float* __restrict__ in, const float* __restrict__ w,
                          float* __restrict__ out)
{
    const int row = blockIdx.x;
    const int t = threadIdx.x;
    float4 v = ((const float4*)(in + (size_t)row * DD))[t];
    float ss = v.x * v.x + v.y * v.y + v.z * v.z + v.w * v.w;
    #pragma unroll
    for (int off = 16; off > 0; off >>= 1) ss += __shfl_xor_sync(0xffffffffu, ss, off);
    __shared__ float ws[8];
    if ((t & 31) == 0) ws[t >> 5] = ss;
    __syncthreads();
    float tot = ws[0] + ws[1] + ws[2] + ws[3] + ws[4] + ws[5] + ws[6] + ws[7];
    const float r = rsqrtf(tot * (1.0f / DD) + 1e-6f);
    float4 wv = ((const float4*)w)[t];
    float4 o;
    o.x = v.x * r * wv.x; o.y = v.y * r * wv.y;
    o.z = v.z * r * wv.z; o.w = v.w * r * wv.w;
    ((float4*)(out + (size_t)row * DD))[t] = o;
}

// ---------------- Vmean: per (b,h) mean of V over all keys ----------------
__global__ void vmean_k()
{
    const int h = blockIdx.x, b = blockIdx.y;
    const int d = threadIdx.x & 63, part = threadIdx.x >> 6;
    const float* vb = g_qkv + 2*QKV_OFF + (size_t)(b * SS) * DD + h * 64;
    float a0 = 0.f, a1 = 0.f;
    int j = part;
    for (; j + 8 <= SS; j += 8) {
        a0 += vb[(size_t)j * DD + d];
        a1 += vb[(size_t)(j + 4) * DD + d];
    }
    for (; j < SS; j += 4) a0 += vb[(size_t)j * DD + d];
    __shared__ float red[256];
    red[threadIdx.x] = a0 + a1;
    __syncthreads();
    if (threadIdx.x < 64)
        g_vmean[(b * HH + h) * 64 + threadIdx.x] =
            (red[threadIdx.x] + red[64 + threadIdx.x] +
             red[128 + threadIdx.x] + red[192 + threadIdx.x]) * (1.f / 1026.f);
}

// ---------------- fused attention (flash-style, fp32) ----------------
// Masked rows (qg >= limit) reproduce the reference's fp32 flush: exactly
// uniform softmax. Fully-masked tiles short-circuit to the Vmean broadcast.
#define ATT_P 65
#define ATT_SMEM_FLOATS (4 * 64 * ATT_P + 3 * 64)

__global__ void __launch_bounds__(256)
attn_k(const int* __restrict__ spd, const float* __restrict__ spde,
       const int* __restrict__ tmlp)
{
    extern __shared__ float smd[];
    float* Qs   = smd;
    float* Ks   = Qs + 64 * ATT_P;
    float* Vs   = Ks + 64 * ATT_P;
    float* St   = Vs + 64 * ATT_P;
    float* rowm = St + 64 * ATT_P;
    float* rowl = rowm + 64;
    float* rowc = rowl + 64;
    __shared__ float sc[32];

    const int tid = threadIdx.x;
    const int qt = blockIdx.x, h = blockIdx.y, b = blockIdx.z;
    const int q0 = qt * 64;
    int nq = SS - q0; if (nq > 64) nq = 64;
    const int limit = tmlp[b] + 2;

    // ---- fully-masked tile: output = Vmean for every row ----
    if (q0 >= limit) {
        const int d = tid & 63, part = tid >> 6;
        const float s = g_vmean[(b * HH + h) * 64 + d];
        for (int qi = part; qi < nq; qi += 4)
            g_att[((size_t)(b * SS + q0 + qi)) * DD + h * 64 + d] = s;
        return;
    }

    if (tid < 32) sc[tid] = spde[tid * HH + h];
    if (tid < 64) { rowm[tid] = -1e30f; rowl[tid] = 0.f; rowc[tid] = 1.f; }

    const float* qb = g_qkv + ((size_t)(b * SS + q0)) * DD + h * 64;
    #pragma unroll
    for (int r = 0; r < 16; r++) {
        const int idx = tid + r * 256;
        const int qi = idx >> 6, d = idx & 63;
        Qs[d * ATT_P + qi] = (qi < nq) ? qb[(size_t)qi * DD + d] : 0.f;
    }

    const int ty = tid >> 4, tx = tid & 15;
    const int i0 = ty << 2, j0 = tx << 2;
    const int wid = tid >> 5, lane = tid & 31;

    float oacc[4][4];
    #pragma unroll
    for (int a = 0; a < 4; a++)
        #pragma unroll
        for (int c = 0; c < 4; c++) oacc[a][c] = 0.f;

    for (int kt = 0; kt < (SS + 63) / 64; kt++) {
        const int k0 = kt * 64;
        int nk = SS - k0; if (nk > 64) nk = 64;
        __syncthreads();

        const float* kb = g_qkv + QKV_OFF   + ((size_t)(b * SS + k0)) * DD + h * 64;
        const float* vb = g_qkv + 2*QKV_OFF + ((size_t)(b * SS + k0)) * DD + h * 64;
        #pragma unroll
        for (int r = 0; r < 16; r++) {
            const int idx = tid + r * 256;
            const int j = idx >> 6, d = idx & 63;
            const bool ok = (j < nk);
            Ks[d * ATT_P + j] = ok ? kb[(size_t)j * DD + d] : 0.f;
            Vs[j * ATT_P + d] = ok ? vb[(size_t)j * DD + d] : 0.f;
        }
        __syncthreads();

        // ---- scores ----
        float sacc[4][4];
        #pragma unroll
        for (int a = 0; a < 4; a++)
            #pragma unroll
            for (int c = 0; c < 4; c++) sacc[a][c] = 0.f;

        #pragma unroll 4
        for (int d = 0; d < 64; d++) {
            float qv0 = Qs[d * ATT_P + i0 + 0];
            float qv1 = Qs[d * ATT_P + i0 + 1];
            float qv2 = Qs[d * ATT_P + i0 + 2];
            float qv3 = Qs[d * ATT_P + i0 + 3];
            float kv0 = Ks[d * ATT_P + j0 + 0];
            float kv1 = Ks[d * ATT_P + j0 + 1];
            float kv2 = Ks[d * ATT_P + j0 + 2];
            float kv3 = Ks[d * ATT_P + j0 + 3];
            sacc[0][0] += qv0 * kv0; sacc[0][1] += qv0 * kv1; sacc[0][2] += qv0 * kv2; sacc[0][3] += qv0 * kv3;
            sacc[1][0] += qv1 * kv0; sacc[1][1] += qv1 * kv1; sacc[1][2] += qv1 * kv2; sacc[1][3] += qv1 * kv3;
            sacc[2][0] += qv2 * kv0; sacc[2][1] += qv2 * kv1; sacc[2][2] += qv2 * kv2; sacc[2][3] += qv2 * kv3;
            sacc[3][0] += qv3 * kv0; sacc[3][1] += qv3 * kv1; sacc[3][2] += qv3 * kv2; sacc[3][3] += qv3 * kv3;
        }

        // ---- scale + bias, write transposed (masked rows overwritten below) ----
        #pragma unroll
        for (int ii = 0; ii < 4; ii++) {
            const int qi = i0 + ii;
            const int qg = q0 + qi;
            const bool qok = (qg < SS);
            #pragma unroll
            for (int jj = 0; jj < 4; jj++) {
                const int jl = j0 + jj;
                const int kg = k0 + jl;
                float o;
                if (!qok || jl >= nk) o = -1e30f;
                else {
                    int id;
                    if (qg >= 2 && kg >= 2)
                        id = spd[((size_t)b * LL + (qg - 2)) * LL + (kg - 2)];
                    else
                        id = (qg == kg) ? 0 : 31;
                    o = sacc[ii][jj] * 0.125f + sc[id];
                }
                St[jl * ATT_P + qi] = o;
            }
        }
        __syncthreads();

        // ---- warp-per-row online softmax (8 warps x 8 rows) ----
        for (int rr = 0; rr < 8; rr++) {
            const int i = wid * 8 + rr;
            if (i >= nq) break;                 // warp-uniform
            const int qg = q0 + i;
            if (qg >= limit) {
                // uniform row: p = 1 (== exp(0-0)), no MUFU
                St[lane * ATT_P + i]        = (lane      < nk) ? 1.f : 0.f;
                St[(lane + 32) * ATT_P + i] = (lane + 32 < nk) ? 1.f : 0.f;
                if (lane == 0) { rowc[i] = 1.f; rowl[i] += (float)nk; }
            } else {
                float v0 = St[lane * ATT_P + i];
                float v1 = St[(lane + 32) * ATT_P + i];
                float m = fmaxf(v0, v1);
                #pragma unroll
                for (int off = 16; off > 0; off >>= 1)
                    m = fmaxf(m, __shfl_xor_sync(0xffffffffu, m, off));
                const float pm = rowm[i];
                const float mt = fmaxf(m, pm);
                const float p0 = __expf(v0 - mt);   // exp(-1e30-mt) underflows to 0
                const float p1 = __expf(v1 - mt);
                St[lane * ATT_P + i]        = p0;
                St[(lane + 32) * ATT_P + i] = p1;
                float s = p0 + p1;
                #pragma unroll
                for (int off = 16; off > 0; off >>= 1)
                    s += __shfl_xor_sync(0xffffffffu, s, off);
                if (lane == 0) {
                    const float corr = __expf(pm - mt);
                    rowl[i] = rowl[i] * corr + s;
                    rowm[i] = mt;
                    rowc[i] = corr;
                }
            }
        }
        __syncthreads();

        // ---- PV accumulate ----
        float cr0 = rowc[i0 + 0], cr1 = rowc[i0 + 1], cr2 = rowc[i0 + 2], cr3 = rowc[i0 + 3];
        #pragma unroll
        for (int c = 0; c < 4; c++) {
            oacc[0][c] *= cr0; oacc[1][c] *= cr1; oacc[2][c] *= cr2; oacc[3][c] *= cr3;
        }
        #pragma unroll 4
        for (int j = 0; j < 64; j++) {
            float p0 = St[j * ATT_P + i0 + 0];
            float p1 = St[j * ATT_P + i0 + 1];
            float p2 = St[j * ATT_P + i0 + 2];
            float p3 = St[j * ATT_P + i0 + 3];
            float v0 = Vs[j * ATT_P + j0 + 0];
            float v1 = Vs[j * ATT_P + j0 + 1];
            float v2 = Vs[j * ATT_P + j0 + 2];
            float v3 = Vs[j * ATT_P + j0 + 3];
            oacc[0][0] += p0 * v0; oacc[0][1] += p0 * v1; oacc[0][2] += p0 * v2; oacc[0][3] += p0 * v3;
            oacc[1][0] += p1 * v0; oacc[1][1] += p1 * v1; oacc[1][2] += p1 * v2; oacc[1][3] += p1 * v3;
            oacc[2][0] += p2 * v0; oacc[2][1] += p2 * v1; oacc[2][2] += p2 * v2; oacc[2][3] += p2 * v3;
            oacc[3][0] += p3 * v0; oacc[3][1] += p3 * v1; oacc[3][2] += p3 * v2; oacc[3][3] += p3 * v3;
        }
    }

    #pragma unroll
    for (int ii = 0; ii < 4; ii++) {
        const int qi = i0 + ii;
        if (qi < nq) {
            const int qg = q0 + qi;
            const float inv = 1.f / rowl[qi];
            float* ob = g_att + ((size_t)(b * SS + qg)) * DD + h * 64 + j0;
            #pragma unroll
            for (int jj = 0; jj < 4; jj++) ob[jj] = oacc[ii][jj] * inv;
        }
    }
}

// ---------------- host driver ----------------
extern "C" void kernel_launch(void* const* d_in, const int* in_sizes, int n_in,
                              void* d_out, int out_size)
{
    const float* graph   = (const float*)d_in[0];
    const float* infeat  = (const float*)d_in[1];
    const float* projW   = (const float*)d_in[2];
    const float* projb   = (const float*)d_in[3];
    const float* sos     = (const float*)d_in[4];
    const float* nodee   = (const float*)d_in[5];
    const float* typee   = (const float*)d_in[6];
    const float* pose    = (const float*)d_in[7];
    const float* spde    = (const float*)d_in[8];
    const float* anorm   = (const float*)d_in[9];
    const float* wq      = (const float*)d_in[10];
    const float* wk      = (const float*)d_in[11];
    const float* wv      = (const float*)d_in[12];
    const float* wo      = (const float*)d_in[13];
    const float* fnorm   = (const float*)d_in[14];
    const float* w1      = (const float*)d_in[15];
    const float* w2      = (const float*)d_in[16];
    const float* w3      = (const float*)d_in[17];
    const float* finaln  = (const float*)d_in[18];
    const float* outW    = (const float*)d_in[19];
    const float* outb    = (const float*)d_in[20];
    const int*   sub     = (const int*)d_in[21];
    const int*   tml     = (const int*)d_in[22];
    const int*   spdidx  = (const int*)d_in[23];
    (void)in_sizes; (void)n_in; (void)out_size;

    float *ph, *px, *pqkv, *patt, *pffn;
    cudaGetSymbolAddress((void**)&ph,   g_h);
    cudaGetSymbolAddress((void**)&px,   g_x);
    cudaGetSymbolAddress((void**)&pqkv, g_qkv);
    cudaGetSymbolAddress((void**)&patt, g_att);
    cudaGetSymbolAddress((void**)&pffn, g_ffn);
    float* pq = pqkv;
    float* pk = pqkv + QKV_OFF;
    float* pv = pqkv + 2*QKV_OFF;
    float* pt1 = pffn;
    float* pt3 = pffn + FFN_OFF;

    const int attSmem = ATT_SMEM_FLOATS * (int)sizeof(float);
    cudaFuncSetAttribute(attn_k, cudaFuncAttributeMaxDynamicSharedMemorySize, attSmem);

    // BM=128 (big-grid GEMMs: FFN up-projections, logits)
    auto gemm = [](const float* A, const float* W, float* C, const float* E,
                   int M, int N, int K, int mode, int arm) {
        dim3 g((N + 127) / 128, (M + 127) / 128);
        gemm_tc<4><<<g, 256>>>(A, W, C, E, M, N, K, mode, arm);
    };
    // BM=64 (small-grid GEMMs: QKV, O, w2, proj — grid >= 256 for 2 CTAs/SM)
    auto gemmS = [](const float* A, const float* W, float* C, const float* E,
                    int M, int N, int K, int mode, int arm) {
        dim3 g((N + 127) / 128, (M + 63) / 64);
        gemm_tc<2><<<g, 256>>>(A, W, C, E, M, N, K, mode, arm);
    };

    // input projection (bias fused) into g_x, then embeddings into g_h
    gemmS(infeat, projW, px, projb, BB * LL, DD, FDIM, 1, 0);
    embed_k<<<MROWS, 256>>>(graph, sos, nodee, typee, pose, sub);

    for (int i = 0; i < NLAYER; i++) {
        const size_t wOff = (size_t)i * DD * DD;
        const size_t fOff = (size_t)i * DD * DFF;

        rmsnorm_k<<<MROWS, 256>>>(ph, anorm + (size_t)i * DD, px);
        gemmS(px, wq + wOff, pq, nullptr, MROWS, DD, DD, 0, 0);
        gemmS(px, wk + wOff, pk, nullptr, MROWS, DD, DD, 0, 0);
        gemmS(px, wv + wOff, pv, nullptr, MROWS, DD, DD, 0, 0);

        vmean_k<<<dim3(HH, BB), 256>>>();
        attn_k<<<dim3((SS + 63) / 64, HH, BB), 256, attSmem>>>(spdidx, spde, tml);

        gemmS(patt, wo + wOff, ph, nullptr, MROWS, DD, DD, 2, 0);  // h += att @ wo

        rmsnorm_k<<<MROWS, 256>>>(ph, fnorm + (size_t)i * DD, px);
        gemm(px, w1 + fOff, pt1, nullptr, MROWS, DFF, DD, 0, 0);   // t1 = x @ w1
        gemm(px, w3 + fOff, pt3, pt1,     MROWS, DFF, DD, 3, 0);   // t3 = silu(t1) * (x @ w3)
        gemmS(pt3, w2 + (size_t)i * DFF * DD, ph, nullptr, MROWS, DD, DFF, 2, 0); // h += t3 @ w2
    }

    rmsnorm_k<<<MROWS, 256>>>(ph, finaln, px);
    // logits: skip graph row via remap; bias fused
    gemm(px, outW, (float*)d_out, outb, OUTROWS, NVOC, DD, 1, 1);
}

// round 16
// speedup vs baseline: 2.1331x; 1.0168x over previous
#include <cuda_runtime.h>
#include <cuda_bf16.h>
#include <math.h>

// ---------------- problem constants ----------------
#define BB     2
#define LL     1024
#define DD     1024
#define HH     16
#define FDIM   512
#define NLAYER 4
#define NVOC   5000
#define DFF    4096
#define SS     1026            // seqlen = 1 (graph) + 1 (sos) + L
#define MROWS  (BB*SS)         // 2052
#define OUTROWS (BB*(SS-1))    // 2050 output rows (skip graph row)

#define QKV_OFF (BB*SS*DD)
#define FFN_OFF (BB*SS*DFF)

// ---------------- scratch (device globals; no allocation allowed) ----------------
__device__ float g_h  [BB*SS*DD];
__device__ float g_x  [BB*SS*DD];
__device__ float g_qkv[3*BB*SS*DD];
__device__ float g_att[BB*SS*DD];
__device__ float g_ffn[2*BB*SS*DFF];
__device__ float g_vmean[BB*HH*64];

// ---------------- tf32 helpers ----------------
__device__ __forceinline__ unsigned tf32cvt(float x) {
    unsigned r;
    asm("cvt.rna.tf32.f32 %0, %1;" : "=r"(r) : "f"(x));
    return r;
}
__device__ __forceinline__ float tf32f(float x) {
    return __uint_as_float(tf32cvt(x));
}
__device__ __forceinline__ void mma_tf32(float* d, const unsigned* a, const unsigned* b) {
    asm volatile(
        "mma.sync.aligned.m16n8k8.row.col.f32.tf32.tf32.f32 "
        "{%0,%1,%2,%3}, {%4,%5,%6,%7}, {%8,%9}, {%0,%1,%2,%3};"
        : "+f"(d[0]), "+f"(d[1]), "+f"(d[2]), "+f"(d[3])
        : "r"(a[0]), "r"(a[1]), "r"(a[2]), "r"(a[3]), "r"(b[0]), "r"(b[1]));
}
__device__ __forceinline__ void ldsm4(unsigned* f, unsigned saddr) {
    asm volatile("ldmatrix.sync.aligned.m8n8.x4.shared.b16 {%0,%1,%2,%3}, [%4];"
        : "=r"(f[0]), "=r"(f[1]), "=r"(f[2]), "=r"(f[3]) : "r"(saddr));
}

// ---------------- TF32 tensor-core GEMM ----------------
// C[M,N] (op) A[M,K] @ W[K,N], K % 16 == 0, N % 4 == 0.
// mode 0: C = A@W
// mode 1: C = A@W + E   (E = bias vector, length N)
// mode 2: C = C + A@W   (residual)
// mode 3: C = silu(E[m,n]) * (A@W)  (E = matrix, same layout as C)
// arm  1: A row remap for logits: arow = (m/1025)*SS + 1 + m%1025
// MF = m-fragments per warp: 4 -> BM=128, 2 -> BM=64 (small-grid occupancy)
#define AST 20    // As row stride in tf32 (80B: LDSM rows hit all 8 bank-quads)
#define BP  132   // Bs2 row pad in float2 (conflict-free LDS.64 per half-warp)

template<int MF>
__global__ void __launch_bounds__(256, 2)
gemm_tc(const float* __restrict__ A, const float* __restrict__ W,
        float* __restrict__ C, const float* __restrict__ E,
        int M, int N, int K, int mode, int arm)
{
    __shared__ unsigned As[2][MF*32][AST];
    // B pairs: Bs2[buf][g][s][c] = (B[g*8+s][c], B[g*8+s+4][c]) as float2
    __shared__ __align__(16) float2 Bs2[2][2][4][BP];

    const int tid = threadIdx.x;
    const int bm = blockIdx.y * (MF * 32);
    const int bn = blockIdx.x * 128;

    // ---- A gmem load indices ----
    const int a_r0 = tid >> 2;            // 0..63
    const int a_c  = (tid & 3) << 2;      // k offset 0/4/8/12

    int am0 = bm + a_r0, am1 = bm + a_r0 + 64;
    const bool av0 = am0 < M;
    const bool av1 = (MF == 4) && (am1 < M);
    if (arm == 1) {
        if (av0) am0 = (am0 / 1025) * SS + 1 + (am0 % 1025);
        if (av1) am1 = (am1 / 1025) * SS + 1 + (am1 % 1025);
    }
    const float* ap0 = A + (size_t)am0 * K + a_c;
    const float* ap1 = A + (size_t)am1 * K + a_c;

    // ---- B gmem load indices: row pair (r0, r0+4), 4 consecutive cols ----
    const int b_j  = tid & 31;            // c0 = 4*b_j
    const int b_rp = tid >> 5;            // 0..7
    const int b_g  = b_rp >> 2;           // ks group 0/1
    const int b_s  = b_rp & 3;            // slot (lk)
    const int b_r0 = b_g * 8 + b_s;       // k row (low of pair)
    const float* bp0 = W + (size_t)b_r0 * N + bn + 4 * b_j;
    const float* bp1 = W + (size_t)(b_r0 + 4) * N + bn + 4 * b_j;
    const bool bv = (bn + 4 * b_j) < N;

    // ---- warp / fragment indices ----
    const int wid = tid >> 5, lane = tid & 31;
    const int wm = (wid >> 2) * (MF * 16); // warp row base
    const int wn = (wid & 3) * 32;         // warp col base
    const int lm = lane >> 2;              // 0..7
    const int lk = lane & 3;               // 0..3

    const int lds_row  = (lane & 7) + ((lane >> 3) & 1) * 8;
    const int lds_bcol = ((lane >> 4) & 1) * 16;
    const unsigned asBase0 = (unsigned)__cvta_generic_to_shared(&As[0][0][0]);
    const unsigned asBase1 = (unsigned)__cvta_generic_to_shared(&As[1][0][0]);

    float acc[MF][4][4];
    #pragma unroll
    for (int i = 0; i < MF; i++)
        #pragma unroll
        for (int j = 0; j < 4; j++)
            #pragma unroll
            for (int r = 0; r < 4; r++) acc[i][j][r] = 0.f;

    const int nkt = K >> 4;
    float4 a4_0, a4_1, bv4_0, bv4_1;

    a4_0 = av0 ? *(const float4*)ap0 : make_float4(0.f,0.f,0.f,0.f);
    if (MF == 4) a4_1 = av1 ? *(const float4*)ap1 : make_float4(0.f,0.f,0.f,0.f);
    bv4_0 = bv ? *(const float4*)bp0 : make_float4(0.f,0.f,0.f,0.f);
    bv4_1 = bv ? *(const float4*)bp1 : make_float4(0.f,0.f,0.f,0.f);

    int buf = 0;
    {   // store tile 0
        uint4 ua0 = { tf32cvt(a4_0.x), tf32cvt(a4_0.y), tf32cvt(a4_0.z), tf32cvt(a4_0.w) };
        *(uint4*)&As[0][a_r0][a_c] = ua0;
        if (MF == 4) {
            uint4 ua1 = { tf32cvt(a4_1.x), tf32cvt(a4_1.y), tf32cvt(a4_1.z), tf32cvt(a4_1.w) };
            *(uint4*)&As[0][a_r0 + 64][a_c] = ua1;
        }
        float2* dst = &Bs2[0][b_g][b_s][4 * b_j];
        dst[0] = make_float2(tf32f(bv4_0.x), tf32f(bv4_1.x));
        dst[1] = make_float2(tf32f(bv4_0.y), tf32f(bv4_1.y));
        dst[2] = make_float2(tf32f(bv4_0.z), tf32f(bv4_1.z));
        dst[3] = make_float2(tf32f(bv4_0.w), tf32f(bv4_1.w));
    }
    __syncthreads();

    for (int kt = 0; kt < nkt; kt++) {
        // gmem prefetch of next tile
        if (kt + 1 < nkt) {
            ap0 += 16; ap1 += 16;
            bp0 += (size_t)16 * N; bp1 += (size_t)16 * N;
            a4_0 = av0 ? *(const float4*)ap0 : make_float4(0.f,0.f,0.f,0.f);
            if (MF == 4) a4_1 = av1 ? *(const float4*)ap1 : make_float4(0.f,0.f,0.f,0.f);
            bv4_0 = bv ? *(const float4*)bp0 : make_float4(0.f,0.f,0.f,0.f);
            bv4_1 = bv ? *(const float4*)bp1 : make_float4(0.f,0.f,0.f,0.f);
        }

        const unsigned asb = buf ? asBase1 : asBase0;

        if (MF == 2) {
            // full fragment hoist: one load burst, then 16 dependency-free MMAs
            unsigned af[2][2][4];
            uint2    bfv[2][4];
            #pragma unroll
            for (int ks = 0; ks < 2; ks++) {
                #pragma unroll
                for (int mt = 0; mt < 2; mt++) {
                    const int r = wm + mt * 16 + lds_row;
                    ldsm4(af[ks][mt], asb + (unsigned)(r * (AST*4) + ks * 32 + lds_bcol));
                }
                #pragma unroll
                for (int nt = 0; nt < 4; nt++)
                    bfv[ks][nt] = *(const uint2*)&Bs2[buf][ks][lk][wn + nt * 8 + lm];
            }
            #pragma unroll
            for (int ks = 0; ks < 2; ks++)
                #pragma unroll
                for (int mt = 0; mt < 2; mt++)
                    #pragma unroll
                    for (int nt = 0; nt < 4; nt++)
                        mma_tf32(acc[mt][nt], af[ks][mt], (const unsigned*)&bfv[ks][nt]);
        } else {
            #pragma unroll
            for (int ks = 0; ks < 2; ks++) {
                unsigned af[4][4];
                uint2    bfv[4];
                #pragma unroll
                for (int mt = 0; mt < 4; mt++) {
                    const int r = wm + mt * 16 + lds_row;
                    ldsm4(af[mt], asb + (unsigned)(r * (AST*4) + ks * 32 + lds_bcol));
                }
                #pragma unroll
                for (int nt = 0; nt < 4; nt++)
                    bfv[nt] = *(const uint2*)&Bs2[buf][ks][lk][wn + nt * 8 + lm];
                #pragma unroll
                for (int mt = 0; mt < 4; mt++)
                    #pragma unroll
                    for (int nt = 0; nt < 4; nt++)
                        mma_tf32(acc[mt][nt], af[mt], (const unsigned*)&bfv[nt]);
            }
        }

        // store prefetched tile into other buffer
        if (kt + 1 < nkt) {
            const int nb = buf ^ 1;
            uint4 ua0 = { tf32cvt(a4_0.x), tf32cvt(a4_0.y), tf32cvt(a4_0.z), tf32cvt(a4_0.w) };
            *(uint4*)&As[nb][a_r0][a_c] = ua0;
            if (MF == 4) {
                uint4 ua1 = { tf32cvt(a4_1.x), tf32cvt(a4_1.y), tf32cvt(a4_1.z), tf32cvt(a4_1.w) };
                *(uint4*)&As[nb][a_r0 + 64][a_c] = ua1;
            }
            float2* dst = &Bs2[nb][b_g][b_s][4 * b_j];
            dst[0] = make_float2(tf32f(bv4_0.x), tf32f(bv4_1.x));
            dst[1] = make_float2(tf32f(bv4_0.y), tf32f(bv4_1.y));
            dst[2] = make_float2(tf32f(bv4_0.z), tf32f(bv4_1.z));
            dst[3] = make_float2(tf32f(bv4_0.w), tf32f(bv4_1.w));
        }
        __syncthreads();
        buf ^= 1;
    }

    // ---- epilogue ----
    #pragma unroll
    for (int mt = 0; mt < MF; mt++) {
        #pragma unroll
        for (int rr = 0; rr < 2; rr++) {
            const int m = bm + wm + mt * 16 + lm + rr * 8;
            if (m >= M) continue;
            const size_t base = (size_t)m * N;
            #pragma unroll
            for (int nt = 0; nt < 4; nt++) {
                const int c = bn + wn + nt * 8 + 2 * lk;
                if (c >= N) continue;
                float v0 = acc[mt][nt][rr * 2 + 0];
                float v1 = acc[mt][nt][rr * 2 + 1];
                if (mode == 1)      { v0 += E[c]; v1 += E[c + 1]; }
                else if (mode == 2) { v0 += C[base + c]; v1 += C[base + c + 1]; }
                else if (mode == 3) {
                    float t0 = E[base + c], t1 = E[base + c + 1];
                    v0 *= t0 / (1.f + __expf(-t0));
                    v1 *= t1 / (1.f + __expf(-t1));
                }
                float2 o; o.x = v0; o.y = v1;
                *(float2*)&C[base + c] = o;
            }
        }
    }
}

// ---------------- embedding assembly ----------------
__device__ __forceinline__ float4 f4add(float4 a, float4 b) {
    a.x += b.x; a.y += b.y; a.z += b.z; a.w += b.w; return a;
}

__global__ void embed_k(const float* __restrict__ gf, const float* __restrict__ sos,
                        const float* __restrict__ nodee, const float* __restrict__ typee,
                        const float* __restrict__ pose, const int* __restrict__ sub)
{
    const int row = blockIdx.x;
    const int b = row / SS, s = row % SS;
    const int t = threadIdx.x;
    const int D4 = DD / 4;

    float4 acc = ((const float4*)pose)[(size_t)s * D4 + t];
    if (s == 0) {
        acc = f4add(acc, ((const float4*)gf)[(size_t)b * D4 + t]);
        acc = f4add(acc, ((const float4*)typee)[D4 + t]);
    } else {
        float4 bv, ne;
        if (s == 1) {
            bv = ((const float4*)sos)[t];
            ne = ((const float4*)nodee)[t];
        } else {
            const int tok = b * LL + (s - 2);
            bv = ((const float4*)g_x)[(size_t)tok * D4 + t];
            ne = ((const float4*)nodee)[(size_t)sub[tok] * D4 + t];
        }
        acc = f4add(acc, bv);
        acc = f4add(acc, ne);
        acc = f4add(acc, ((const float4*)typee)[t]);
    }
    ((float4*)g_h)[(size_t)row * D4 + t] = acc;
}

// ---------------- RMSNorm ----------------
__global__ void rmsnorm_k(const float* __restrict__ in, const float* __restrict__ w,
                          float* __restrict__ out)
{
    const int row = blockIdx.x;
    const int t = threadIdx.x;
    float4 v = ((const float4*)(in + (size_t)row * DD))[t];
    float ss = v.x * v.x + v.y * v.y + v.z * v.z + v.w * v.w;
    #pragma unroll
    for (int off = 16; off > 0; off >>= 1) ss += __shfl_xor_sync(0xffffffffu, ss, off);
    __shared__ float ws[8];
    if ((t & 31) == 0) ws[t >> 5] = ss;
    __syncthreads();
    float tot = ws[0] + ws[1] + ws[2] + ws[3] + ws[4] + ws[5] + ws[6] + ws[7];
    const float r = rsqrtf(tot * (1.0f / DD) + 1e-6f);
    float4 wv = ((const float4*)w)[t];
    float4 o;
    o.x = v.x * r * wv.x; o.y = v.y * r * wv.y;
    o.z = v.z * r * wv.z; o.w = v.w * r * wv.w;
    ((float4*)(out + (size_t)row * DD))[t] = o;
}

// ---------------- Vmean: per (b,h) mean of V over all keys ----------------
__global__ void vmean_k()
{
    const int h = blockIdx.x, b = blockIdx.y;
    const int d = threadIdx.x & 63, part = threadIdx.x >> 6;
    const float* vb = g_qkv + 2*QKV_OFF + (size_t)(b * SS) * DD + h * 64;
    float a0 = 0.f, a1 = 0.f;
    int j = part;
    for (; j + 8 <= SS; j += 8) {
        a0 += vb[(size_t)j * DD + d];
        a1 += vb[(size_t)(j + 4) * DD + d];
    }
    for (; j < SS; j += 4) a0 += vb[(size_t)j * DD + d];
    __shared__ float red[256];
    red[threadIdx.x] = a0 + a1;
    __syncthreads();
    if (threadIdx.x < 64)
        g_vmean[(b * HH + h) * 64 + threadIdx.x] =
            (red[threadIdx.x] + red[64 + threadIdx.x] +
             red[128 + threadIdx.x] + red[192 + threadIdx.x]) * (1.f / 1026.f);
}

// ---------------- fused attention (flash-style, fp32) ----------------
// Masked rows (qg >= limit) reproduce the reference's fp32 flush: exactly
// uniform softmax. Fully-masked tiles short-circuit to the Vmean broadcast.
#define ATT_P 65
#define ATT_SMEM_FLOATS (4 * 64 * ATT_P + 3 * 64)

__global__ void __launch_bounds__(256)
attn_k(const int* __restrict__ spd, const float* __restrict__ spde,
       const int* __restrict__ tmlp)
{
    extern __shared__ float smd[];
    float* Qs   = smd;
    float* Ks   = Qs + 64 * ATT_P;
    float* Vs   = Ks + 64 * ATT_P;
    float* St   = Vs + 64 * ATT_P;
    float* rowm = St + 64 * ATT_P;
    float* rowl = rowm + 64;
    float* rowc = rowl + 64;
    __shared__ float sc[32];

    const int tid = threadIdx.x;
    const int qt = blockIdx.x, h = blockIdx.y, b = blockIdx.z;
    const int q0 = qt * 64;
    int nq = SS - q0; if (nq > 64) nq = 64;
    const int limit = tmlp[b] + 2;

    // ---- fully-masked tile: output = Vmean for every row ----
    if (q0 >= limit) {
        const int d = tid & 63, part = tid >> 6;
        const float s = g_vmean[(b * HH + h) * 64 + d];
        for (int qi = part; qi < nq; qi += 4)
            g_att[((size_t)(b * SS + q0 + qi)) * DD + h * 64 + d] = s;
        return;
    }

    if (tid < 32) sc[tid] = spde[tid * HH + h];
    if (tid < 64) { rowm[tid] = -1e30f; rowl[tid] = 0.f; rowc[tid] = 1.f; }

    const float* qb = g_qkv + ((size_t)(b * SS + q0)) * DD + h * 64;
    #pragma unroll
    for (int r = 0; r < 16; r++) {
        const int idx = tid + r * 256;
        const int qi = idx >> 6, d = idx & 63;
        Qs[d * ATT_P + qi] = (qi < nq) ? qb[(size_t)qi * DD + d] : 0.f;
    }

    const int ty = tid >> 4, tx = tid & 15;
    const int i0 = ty << 2, j0 = tx << 2;
    const int wid = tid >> 5, lane = tid & 31;

    float oacc[4][4];
    #pragma unroll
    for (int a = 0; a < 4; a++)
        #pragma unroll
        for (int c = 0; c < 4; c++) oacc[a][c] = 0.f;

    for (int kt = 0; kt < (SS + 63) / 64; kt++) {
        const int k0 = kt * 64;
        int nk = SS - k0; if (nk > 64) nk = 64;
        __syncthreads();

        const float* kb = g_qkv + QKV_OFF   + ((size_t)(b * SS + k0)) * DD + h * 64;
        const float* vb = g_qkv + 2*QKV_OFF + ((size_t)(b * SS + k0)) * DD + h * 64;
        #pragma unroll
        for (int r = 0; r < 16; r++) {
            const int idx = tid + r * 256;
            const int j = idx >> 6, d = idx & 63;
            const bool ok = (j < nk);
            Ks[d * ATT_P + j] = ok ? kb[(size_t)j * DD + d] : 0.f;
            Vs[j * ATT_P + d] = ok ? vb[(size_t)j * DD + d] : 0.f;
        }
        __syncthreads();

        // ---- scores ----
        float sacc[4][4];
        #pragma unroll
        for (int a = 0; a < 4; a++)
            #pragma unroll
            for (int c = 0; c < 4; c++) sacc[a][c] = 0.f;

        #pragma unroll 4
        for (int d = 0; d < 64; d++) {
            float qv0 = Qs[d * ATT_P + i0 + 0];
            float qv1 = Qs[d * ATT_P + i0 + 1];
            float qv2 = Qs[d * ATT_P + i0 + 2];
            float qv3 = Qs[d * ATT_P + i0 + 3];
            float kv0 = Ks[d * ATT_P + j0 + 0];
            float kv1 = Ks[d * ATT_P + j0 + 1];
            float kv2 = Ks[d * ATT_P + j0 + 2];
            float kv3 = Ks[d * ATT_P + j0 + 3];
            sacc[0][0] += qv0 * kv0; sacc[0][1] += qv0 * kv1; sacc[0][2] += qv0 * kv2; sacc[0][3] += qv0 * kv3;
            sacc[1][0] += qv1 * kv0; sacc[1][1] += qv1 * kv1; sacc[1][2] += qv1 * kv2; sacc[1][3] += qv1 * kv3;
            sacc[2][0] += qv2 * kv0; sacc[2][1] += qv2 * kv1; sacc[2][2] += qv2 * kv2; sacc[2][3] += qv2 * kv3;
            sacc[3][0] += qv3 * kv0; sacc[3][1] += qv3 * kv1; sacc[3][2] += qv3 * kv2; sacc[3][3] += qv3 * kv3;
        }

        // ---- scale + bias, write transposed (masked rows overwritten below) ----
        #pragma unroll
        for (int ii = 0; ii < 4; ii++) {
            const int qi = i0 + ii;
            const int qg = q0 + qi;
            const bool qok = (qg < SS);
            #pragma unroll
            for (int jj = 0; jj < 4; jj++) {
                const int jl = j0 + jj;
                const int kg = k0 + jl;
                float o;
                if (!qok || jl >= nk) o = -1e30f;
                else {
                    int id;
                    if (qg >= 2 && kg >= 2)
                        id = spd[((size_t)b * LL + (qg - 2)) * LL + (kg - 2)];
                    else
                        id = (qg == kg) ? 0 : 31;
                    o = sacc[ii][jj] * 0.125f + sc[id];
                }
                St[jl * ATT_P + qi] = o;
            }
        }
        __syncthreads();

        // ---- warp-per-row online softmax (8 warps x 8 rows) ----
        for (int rr = 0; rr < 8; rr++) {
            const int i = wid * 8 + rr;
            if (i >= nq) break;                 // warp-uniform
            const int qg = q0 + i;
            if (qg >= limit) {
                St[lane * ATT_P + i]        = (lane      < nk) ? 1.f : 0.f;
                St[(lane + 32) * ATT_P + i] = (lane + 32 < nk) ? 1.f : 0.f;
                if (lane == 0) { rowc[i] = 1.f; rowl[i] += (float)nk; }
            } else {
                float v0 = St[lane * ATT_P + i];
                float v1 = St[(lane + 32) * ATT_P + i];
                float m = fmaxf(v0, v1);
                #pragma unroll
                for (int off = 16; off > 0; off >>= 1)
                    m = fmaxf(m, __shfl_xor_sync(0xffffffffu, m, off));
                const float pm = rowm[i];
                const float mt = fmaxf(m, pm);
                const float p0 = __expf(v0 - mt);
                const float p1 = __expf(v1 - mt);
                St[lane * ATT_P + i]        = p0;
                St[(lane + 32) * ATT_P + i] = p1;
                float s = p0 + p1;
                #pragma unroll
                for (int off = 16; off > 0; off >>= 1)
                    s += __shfl_xor_sync(0xffffffffu, s, off);
                if (lane == 0) {
                    const float corr = __expf(pm - mt);
                    rowl[i] = rowl[i] * corr + s;
                    rowm[i] = mt;
                    rowc[i] = corr;
                }
            }
        }
        __syncthreads();

        // ---- PV accumulate ----
        float cr0 = rowc[i0 + 0], cr1 = rowc[i0 + 1], cr2 = rowc[i0 + 2], cr3 = rowc[i0 + 3];
        #pragma unroll
        for (int c = 0; c < 4; c++) {
            oacc[0][c] *= cr0; oacc[1][c] *= cr1; oacc[2][c] *= cr2; oacc[3][c] *= cr3;
        }
        #pragma unroll 4
        for (int j = 0; j < 64; j++) {
            float p0 = St[j * ATT_P + i0 + 0];
            float p1 = St[j * ATT_P + i0 + 1];
            float p2 = St[j * ATT_P + i0 + 2];
            float p3 = St[j * ATT_P + i0 + 3];
            float v0 = Vs[j * ATT_P + j0 + 0];
            float v1 = Vs[j * ATT_P + j0 + 1];
            float v2 = Vs[j * ATT_P + j0 + 2];
            float v3 = Vs[j * ATT_P + j0 + 3];
            oacc[0][0] += p0 * v0; oacc[0][1] += p0 * v1; oacc[0][2] += p0 * v2; oacc[0][3] += p0 * v3;
            oacc[1][0] += p1 * v0; oacc[1][1] += p1 * v1; oacc[1][2] += p1 * v2; oacc[1][3] += p1 * v3;
            oacc[2][0] += p2 * v0; oacc[2][1] += p2 * v1; oacc[2][2] += p2 * v2; oacc[2][3] += p2 * v3;
            oacc[3][0] += p3 * v0; oacc[3][1] += p3 * v1; oacc[3][2] += p3 * v2; oacc[3][3] += p3 * v3;
        }
    }

    #pragma unroll
    for (int ii = 0; ii < 4; ii++) {
        const int qi = i0 + ii;
        if (qi < nq) {
            const int qg = q0 + qi;
            const float inv = 1.f / rowl[qi];
            float* ob = g_att + ((size_t)(b * SS + qg)) * DD + h * 64 + j0;
            #pragma unroll
            for (int jj = 0; jj < 4; jj++) ob[jj] = oacc[ii][jj] * inv;
        }
    }
}

// ---------------- host driver ----------------
extern "C" void kernel_launch(void* const* d_in, const int* in_sizes, int n_in,
                              void* d_out, int out_size)
{
    const float* graph   = (const float*)d_in[0];
    const float* infeat  = (const float*)d_in[1];
    const float* projW   = (const float*)d_in[2];
    const float* projb   = (const float*)d_in[3];
    const float* sos     = (const float*)d_in[4];
    const float* nodee   = (const float*)d_in[5];
    const float* typee   = (const float*)d_in[6];
    const float* pose    = (const float*)d_in[7];
    const float* spde    = (const float*)d_in[8];
    const float* anorm   = (const float*)d_in[9];
    const float* wq      = (const float*)d_in[10];
    const float* wk      = (const float*)d_in[11];
    const float* wv      = (const float*)d_in[12];
    const float* wo      = (const float*)d_in[13];
    const float* fnorm   = (const float*)d_in[14];
    const float* w1      = (const float*)d_in[15];
    const float* w2      = (const float*)d_in[16];
    const float* w3      = (const float*)d_in[17];
    const float* finaln  = (const float*)d_in[18];
    const float* outW    = (const float*)d_in[19];
    const float* outb    = (const float*)d_in[20];
    const int*   sub     = (const int*)d_in[21];
    const int*   tml     = (const int*)d_in[22];
    const int*   spdidx  = (const int*)d_in[23];
    (void)in_sizes; (void)n_in; (void)out_size;

    float *ph, *px, *pqkv, *patt, *pffn;
    cudaGetSymbolAddress((void**)&ph,   g_h);
    cudaGetSymbolAddress((void**)&px,   g_x);
    cudaGetSymbolAddress((void**)&pqkv, g_qkv);
    cudaGetSymbolAddress((void**)&patt, g_att);
    cudaGetSymbolAddress((void**)&pffn, g_ffn);
    float* pq = pqkv;
    float* pk = pqkv + QKV_OFF;
    float* pv = pqkv + 2*QKV_OFF;
    float* pt1 = pffn;
    float* pt3 = pffn + FFN_OFF;

    const int attSmem = ATT_SMEM_FLOATS * (int)sizeof(float);
    cudaFuncSetAttribute(attn_k, cudaFuncAttributeMaxDynamicSharedMemorySize, attSmem);

    // BM=128 (big-grid GEMMs: FFN up-projections, logits)
    auto gemm = [](const float* A, const float* W, float* C, const float* E,
                   int M, int N, int K, int mode, int arm) {
        dim3 g((N + 127) / 128, (M + 127) / 128);
        gemm_tc<4><<<g, 256>>>(A, W, C, E, M, N, K, mode, arm);
    };
    // BM=64 (small-grid GEMMs: QKV, O, w2, proj — grid >= 256 for 2 CTAs/SM)
    auto gemmS = [](const float* A, const float* W, float* C, const float* E,
                    int M, int N, int K, int mode, int arm) {
        dim3 g((N + 127) / 128, (M + 63) / 64);
        gemm_tc<2><<<g, 256>>>(A, W, C, E, M, N, K, mode, arm);
    };

    // input projection (bias fused) into g_x, then embeddings into g_h
    gemmS(infeat, projW, px, projb, BB * LL, DD, FDIM, 1, 0);
    embed_k<<<MROWS, 256>>>(graph, sos, nodee, typee, pose, sub);

    for (int i = 0; i < NLAYER; i++) {
        const size_t wOff = (size_t)i * DD * DD;
        const size_t fOff = (size_t)i * DD * DFF;

        rmsnorm_k<<<MROWS, 256>>>(ph, anorm + (size_t)i * DD, px);
        gemmS(px, wq + wOff, pq, nullptr, MROWS, DD, DD, 0, 0);
        gemmS(px, wk + wOff, pk, nullptr, MROWS, DD, DD, 0, 0);
        gemmS(px, wv + wOff, pv, nullptr, MROWS, DD, DD, 0, 0);

        vmean_k<<<dim3(HH, BB), 256>>>();
        attn_k<<<dim3((SS + 63) / 64, HH, BB), 256, attSmem>>>(spdidx, spde, tml);

        gemmS(patt, wo + wOff, ph, nullptr, MROWS, DD, DD, 2, 0);  // h += att @ wo

        rmsnorm_k<<<MROWS, 256>>>(ph, fnorm + (size_t)i * DD, px);
        gemm(px, w1 + fOff, pt1, nullptr, MROWS, DFF, DD, 0, 0);   // t1 = x @ w1
        gemm(px, w3 + fOff, pt3, pt1,     MROWS, DFF, DD, 3, 0);   // t3 = silu(t1) * (x @ w3)
        gemmS(pt3, w2 + (size_t)i * DFF * DD, ph, nullptr, MROWS, DD, DFF, 2, 0); // h += t3 @ w2
    }

    rmsnorm_k<<<MROWS, 256>>>(ph, finaln, px);
    // logits: skip graph row via remap; bias fused
    gemm(px, outW, (float*)d_out, outb, OUTROWS, NVOC, DD, 1, 1);
}

// round 17
// speedup vs baseline: 2.2597x; 1.0594x over previous
#include <cuda_runtime.h>
#include <cuda_bf16.h>
#include <math.h>

// ---------------- problem constants ----------------
#define BB     2
#define LL     1024
#define DD     1024
#define HH     16
#define FDIM   512
#define NLAYER 4
#define NVOC   5000
#define DFF    4096
#define SS     1026            // seqlen = 1 (graph) + 1 (sos) + L
#define MROWS  (BB*SS)         // 2052
#define OUTROWS (BB*(SS-1))    // 2050 output rows (skip graph row)

#define QKV_OFF (BB*SS*DD)
#define FFN_OFF (BB*SS*DFF)

// ---------------- scratch (device globals; no allocation allowed) ----------------
__device__ float g_h  [BB*SS*DD];
__device__ float g_x  [BB*SS*DD];
__device__ float g_qkv[3*BB*SS*DD];
__device__ float g_att[BB*SS*DD];
__device__ float g_ffn[2*BB*SS*DFF];
__device__ float g_vmean[BB*HH*64];

// tf32-rounded operand pool (weights + infeat), offsets in floats
#define OFF_INF   0
#define N_INF     (BB*LL*FDIM)                 // 1048576
#define OFF_PROJ  (OFF_INF + N_INF)
#define N_PROJ    (FDIM*DD)                    // 524288
#define OFF_WQ    (OFF_PROJ + N_PROJ)
#define N_W4      (NLAYER*DD*DD)               // 4194304
#define OFF_WK    (OFF_WQ + N_W4)
#define OFF_WV    (OFF_WK + N_W4)
#define OFF_WO    (OFF_WV + N_W4)
#define OFF_W1    (OFF_WO + N_W4)
#define N_WF      (NLAYER*DD*DFF)              // 16777216
#define OFF_W3    (OFF_W1 + N_WF)
#define OFF_W2    (OFF_W3 + N_WF)
#define OFF_OUTW  (OFF_W2 + N_WF)
#define N_OUTW    (DD*NVOC)                    // 5120000
#define WT_TOTAL  (OFF_OUTW + N_OUTW)          // 73801728 floats (~295MB)
__device__ float g_wt[WT_TOTAL];

// ---------------- tf32 helpers ----------------
__device__ __forceinline__ unsigned tf32cvt(float x) {
    unsigned r;
    asm("cvt.rna.tf32.f32 %0, %1;" : "=r"(r) : "f"(x));
    return r;
}
__device__ __forceinline__ float tf32f(float x) {
    return __uint_as_float(tf32cvt(x));
}
__device__ __forceinline__ void mma_tf32(float* d, const unsigned* a, const unsigned* b) {
    asm volatile(
        "mma.sync.aligned.m16n8k8.row.col.f32.tf32.tf32.f32 "
        "{%0,%1,%2,%3}, {%4,%5,%6,%7}, {%8,%9}, {%0,%1,%2,%3};"
        : "+f"(d[0]), "+f"(d[1]), "+f"(d[2]), "+f"(d[3])
        : "r"(a[0]), "r"(a[1]), "r"(a[2]), "r"(a[3]), "r"(b[0]), "r"(b[1]));
}
__device__ __forceinline__ void ldsm4(unsigned* f, unsigned saddr) {
    asm volatile("ldmatrix.sync.aligned.m8n8.x4.shared.b16 {%0,%1,%2,%3}, [%4];"
        : "=r"(f[0]), "=r"(f[1]), "=r"(f[2]), "=r"(f[3]) : "r"(saddr));
}
__device__ __forceinline__ void cpa16(unsigned dst, const float* src, int nbytes) {
    asm volatile("cp.async.cg.shared.global [%0], [%1], 16, %2;"
        :: "r"(dst), "l"(src), "r"(nbytes));
}
#define CPA_COMMIT()  asm volatile("cp.async.commit_group;")
#define CPA_WAIT2()   asm volatile("cp.async.wait_group 2;")

// ---------------- operand rounding pass (weights/infeat -> tf32 bits) ----------------
__global__ void cvt_k(const float4* __restrict__ src, float4* __restrict__ dst, int n4)
{
    int i = blockIdx.x * blockDim.x + threadIdx.x;
    const int stride = gridDim.x * blockDim.x;
    for (; i < n4; i += stride) {
        float4 v = src[i];
        dst[i] = make_float4(tf32f(v.x), tf32f(v.y), tf32f(v.z), tf32f(v.w));
    }
}

// ---------------- TF32 tensor-core GEMM, cp.async 4-stage pipeline ----------------
// All A/W operands must already be tf32-rounded bit patterns in gmem.
// C[M,N] (op) A[M,K] @ W[K,N], K % 16 == 0, N % 4 == 0.
// mode 0: C = A@W                    mode 1: C = A@W + E (bias vec)
// mode 2: C += A@W                   mode 3: C = silu(E) * (A@W), output tf32-rounded
// arm 1: logits row remap.
// MF=2 -> BM=64, MF=4 -> BM=128.
#define AST 20     // A row stride (LDSM rows hit all 8 bank-quads)
#define BSTF 136   // B row stride (scalar LDS conflict-free: 8k+c distinct)
#define STAGES 4

template<int MF>
__global__ void __launch_bounds__(256, 2)
gemm_tc(const float* __restrict__ A, const float* __restrict__ W,
        float* __restrict__ C, const float* __restrict__ E,
        int M, int N, int K, int mode, int arm)
{
    extern __shared__ char smraw[];
    const int ABYTES = MF * 32 * AST * 4;   // per-stage A bytes
    const int BBYTES = 16 * BSTF * 4;       // per-stage B bytes
    float* BsBase = (float*)(smraw + STAGES * ABYTES);
    const unsigned asU = (unsigned)__cvta_generic_to_shared(smraw);
    const unsigned bsU = (unsigned)__cvta_generic_to_shared(BsBase);

    const int tid = threadIdx.x;
    const int bm = blockIdx.y * (MF * 32);
    const int bn = blockIdx.x * 128;

    // ---- A chunk indices: row = tid>>2 (0..63), kc = (tid&3)*4 ----
    const int a_row = tid >> 2;
    const int a_kc  = (tid & 3) << 2;
    int am0 = bm + a_row, am1 = bm + a_row + 64;
    const bool av0 = am0 < M;
    const bool av1 = (MF == 4) && (am1 < M);
    if (arm == 1) {
        if (av0) am0 = (am0 / 1025) * SS + 1 + (am0 % 1025);
        if (av1) am1 = (am1 / 1025) * SS + 1 + (am1 % 1025);
    }
    const float* ap0 = A + (size_t)(av0 ? am0 : 0) * K + a_kc;
    const float* ap1 = A + (size_t)(av1 ? am1 : 0) * K + a_kc;
    const int an0 = av0 ? 16 : 0;
    const int an1 = av1 ? 16 : 0;
    const unsigned aDst0 = asU + (unsigned)((a_row * AST + a_kc) * 4);
    const unsigned aDst1 = aDst0 + 64 * AST * 4;

    // ---- B chunk indices: k = tid>>5 (0..7; +8 second), c = (tid&31)*4 ----
    const int b_k = tid >> 5;
    const int b_c = (tid & 31) << 2;
    const float* bp = W + (size_t)b_k * N + bn + b_c;
    const int bnn = (bn + b_c) < N ? 16 : 0;
    const unsigned bDst0 = bsU + (unsigned)((b_k * BSTF + b_c) * 4);
    const unsigned bDst1 = bDst0 + 8 * BSTF * 4;

    // ---- warp / fragment indices ----
    const int wid = tid >> 5, lane = tid & 31;
    const int wm = (wid >> 2) * (MF * 16);
    const int wn = (wid & 3) * 32;
    const int lm = lane >> 2;
    const int lk = lane & 3;
    const int lds_row  = (lane & 7) + ((lane >> 3) & 1) * 8;
    const int lds_bcol = ((lane >> 4) & 1) * 16;

    float acc[MF][4][4];
    #pragma unroll
    for (int i = 0; i < MF; i++)
        #pragma unroll
        for (int j = 0; j < 4; j++)
            #pragma unroll
            for (int r = 0; r < 4; r++) acc[i][j][r] = 0.f;

    const int nkt = K >> 4;

    // ---- issue stage: copy k-tile kt into ring slot s ----
    auto issue = [&](int kt, int s) {
        cpa16(aDst0 + s * ABYTES, ap0 + (size_t)kt * 16, an0);
        if (MF == 4) cpa16(aDst1 + s * ABYTES, ap1 + (size_t)kt * 16, an1);
        const float* b = bp + (size_t)kt * 16 * N;
        cpa16(bDst0 + s * BBYTES, b, bnn);
        cpa16(bDst1 + s * BBYTES, b + (size_t)8 * N, bnn);
        CPA_COMMIT();
    };

    issue(0, 0); issue(1, 1); issue(2, 2);

    for (int kt = 0; kt < nkt; kt++) {
        CPA_WAIT2();
        __syncthreads();

        if (kt + 3 < nkt) issue(kt + 3, (kt + 3) & 3);
        else CPA_COMMIT();                  // keep group count uniform

        const int s = kt & 3;
        const unsigned asb = asU + s * ABYTES;
        const float* Bst = BsBase + s * (16 * BSTF);

        if (MF == 2) {
            unsigned af[2][2][4], bf[2][4][2];
            #pragma unroll
            for (int ks = 0; ks < 2; ks++) {
                #pragma unroll
                for (int mt = 0; mt < 2; mt++) {
                    const int r = wm + mt * 16 + lds_row;
                    ldsm4(af[ks][mt], asb + (unsigned)(r * (AST*4) + ks * 32 + lds_bcol));
                }
                #pragma unroll
                for (int nt = 0; nt < 4; nt++) {
                    const int c = wn + nt * 8 + lm;
                    bf[ks][nt][0] = __float_as_uint(Bst[(ks * 8 + lk    ) * BSTF + c]);
                    bf[ks][nt][1] = __float_as_uint(Bst[(ks * 8 + lk + 4) * BSTF + c]);
                }
            }
            #pragma unroll
            for (int ks = 0; ks < 2; ks++)
                #pragma unroll
                for (int mt = 0; mt < 2; mt++)
                    #pragma unroll
                    for (int nt = 0; nt < 4; nt++)
                        mma_tf32(acc[mt][nt], af[ks][mt], bf[ks][nt]);
        } else {
            #pragma unroll
            for (int ks = 0; ks < 2; ks++) {
                unsigned af[4][4], bf[4][2];
                #pragma unroll
                for (int mt = 0; mt < 4; mt++) {
                    const int r = wm + mt * 16 + lds_row;
                    ldsm4(af[mt], asb + (unsigned)(r * (AST*4) + ks * 32 + lds_bcol));
                }
                #pragma unroll
                for (int nt = 0; nt < 4; nt++) {
                    const int c = wn + nt * 8 + lm;
                    bf[nt][0] = __float_as_uint(Bst[(ks * 8 + lk    ) * BSTF + c]);
                    bf[nt][1] = __float_as_uint(Bst[(ks * 8 + lk + 4) * BSTF + c]);
                }
                #pragma unroll
                for (int mt = 0; mt < 4; mt++)
                    #pragma unroll
                    for (int nt = 0; nt < 4; nt++)
                        mma_tf32(acc[mt][nt], af[mt], bf[nt]);
            }
        }
    }

    // ---- epilogue ----
    #pragma unroll
    for (int mt = 0; mt < MF; mt++) {
        #pragma unroll
        for (int rr = 0; rr < 2; rr++) {
            const int m = bm + wm + mt * 16 + lm + rr * 8;
            if (m >= M) continue;
            const size_t base = (size_t)m * N;
            #pragma unroll
            for (int nt = 0; nt < 4; nt++) {
                const int c = bn + wn + nt * 8 + 2 * lk;
                if (c >= N) continue;
                float v0 = acc[mt][nt][rr * 2 + 0];
                float v1 = acc[mt][nt][rr * 2 + 1];
                if (mode == 1)      { v0 += E[c]; v1 += E[c + 1]; }
                else if (mode == 2) { v0 += C[base + c]; v1 += C[base + c + 1]; }
                else if (mode == 3) {
                    float t0 = E[base + c], t1 = E[base + c + 1];
                    v0 = tf32f(v0 * (t0 / (1.f + __expf(-t0))));  // next GEMM's A operand
                    v1 = tf32f(v1 * (t1 / (1.f + __expf(-t1))));
                }
                float2 o; o.x = v0; o.y = v1;
                *(float2*)&C[base + c] = o;
            }
        }
    }
}

// ---------------- embedding assembly ----------------
__device__ __forceinline__ float4 f4add(float4 a, float4 b) {
    a.x += b.x; a.y += b.y; a.z += b.z; a.w += b.w; return a;
}

__global__ void embed_k(const float* __restrict__ gf, const float* __restrict__ sos,
                        const float* __restrict__ nodee, const float* __restrict__ typee,
                        const float* __restrict__ pose, const int* __restrict__ sub)
{
    const int row = blockIdx.x;
    const int b = row / SS, s = row % SS;
    const int t = threadIdx.x;
    const int D4 = DD / 4;

    float4 acc = ((const float4*)pose)[(size_t)s * D4 + t];
    if (s == 0) {
        acc = f4add(acc, ((const float4*)gf)[(size_t)b * D4 + t]);
        acc = f4add(acc, ((const float4*)typee)[D4 + t]);
    } else {
        float4 bv, ne;
        if (s == 1) {
            bv = ((const float4*)sos)[t];
            ne = ((const float4*)nodee)[t];
        } else {
            const int tok = b * LL + (s - 2);
            bv = ((const float4*)g_x)[(size_t)tok * D4 + t];
            ne = ((const float4*)nodee)[(size_t)sub[tok] * D4 + t];
        }
        acc = f4add(acc, bv);
        acc = f4add(acc, ne);
        acc = f4add(acc, ((const float4*)typee)[t]);
    }
    ((float4*)g_h)[(size_t)row * D4 + t] = acc;
}

// ---------------- RMSNorm (output tf32-rounded: it always feeds a GEMM) ----------------
__global__ void rmsnorm_k(const float* __restrict__ in, const float* __restrict__ w,
                          float* __restrict__ out)
{
    const int row = blockIdx.x;
    const int t = threadIdx.x;
    float4 v = ((const float4*)(in + (size_t)row * DD))[t];
    float ss = v.x * v.x + v.y * v.y + v.z * v.z + v.w * v.w;
    #pragma unroll
    for (int off = 16; off > 0; off >>= 1) ss += __shfl_xor_sync(0xffffffffu, ss, off);
    __shared__ float ws[8];
    if ((t & 31) == 0) ws[t >> 5] = ss;
    __syncthreads();
    float tot = ws[0] + ws[1] + ws[2] + ws[3] + ws[4] + ws[5] + ws[6] + ws[7];
    const float r = rsqrtf(tot * (1.0f / DD) + 1e-6f);
    float4 wv = ((const float4*)w)[t];
    float4 o;
    o.x = tf32f(v.x * r * wv.x); o.y = tf32f(v.y * r * wv.y);
    o.z = tf32f(v.z * r * wv.z); o.w = tf32f(v.w * r * wv.w);
    ((float4*)(out + (size_t)row * DD))[t] = o;
}

// ---------------- Vmean: per (b,h) mean of V over all keys ----------------
__global__ void vmean_k()
{
    const int h = blockIdx.x, b = blockIdx.y;
    const int d = threadIdx.x & 63, part = threadIdx.x >> 6;
    const float* vb = g_qkv + 2*QKV_OFF + (size_t)(b * SS) * DD + h * 64;
    float a0 = 0.f, a1 = 0.f;
    int j = part;
    for (; j + 8 <= SS; j += 8) {
        a0 += vb[(size_t)j * DD + d];
        a1 += vb[(size_t)(j + 4) * DD + d];
    }
    for (; j < SS; j += 4) a0 += vb[(size_t)j * DD + d];
    __shared__ float red[256];
    red[threadIdx.x] = a0 + a1;
    __syncthreads();
    if (threadIdx.x < 64)
        g_vmean[(b * HH + h) * 64 + threadIdx.x] =
            (red[threadIdx.x] + red[64 + threadIdx.x] +
             red[128 + threadIdx.x] + red[192 + threadIdx.x]) * (1.f / 1026.f);
}

// ---------------- fused attention (flash-style, fp32; output tf32-rounded) ----------------
#define ATT_P 65
#define ATT_SMEM_FLOATS (4 * 64 * ATT_P + 3 * 64)

__global__ void __launch_bounds__(256)
attn_k(const int* __restrict__ spd, const float* __restrict__ spde,
       const int* __restrict__ tmlp)
{
    extern __shared__ float smd[];
    float* Qs   = smd;
    float* Ks   = Qs + 64 * ATT_P;
    float* Vs   = Ks + 64 * ATT_P;
    float* St   = Vs + 64 * ATT_P;
    float* rowm = St + 64 * ATT_P;
    float* rowl = rowm + 64;
    float* rowc = rowl + 64;
    __shared__ float sc[32];

    const int tid = threadIdx.x;
    const int qt = blockIdx.x, h = blockIdx.y, b = blockIdx.z;
    const int q0 = qt * 64;
    int nq = SS - q0; if (nq > 64) nq = 64;
    const int limit = tmlp[b] + 2;

    // ---- fully-masked tile: output = Vmean for every row ----
    if (q0 >= limit) {
        const int d = tid & 63, part = tid >> 6;
        const float s = tf32f(g_vmean[(b * HH + h) * 64 + d]);
        for (int qi = part; qi < nq; qi += 4)
            g_att[((size_t)(b * SS + q0 + qi)) * DD + h * 64 + d] = s;
        return;
    }

    if (tid < 32) sc[tid] = spde[tid * HH + h];
    if (tid < 64) { rowm[tid] = -1e30f; rowl[tid] = 0.f; rowc[tid] = 1.f; }

    const float* qb = g_qkv + ((size_t)(b * SS + q0)) * DD + h * 64;
    #pragma unroll
    for (int r = 0; r < 16; r++) {
        const int idx = tid + r * 256;
        const int qi = idx >> 6, d = idx & 63;
        Qs[d * ATT_P + qi] = (qi < nq) ? qb[(size_t)qi * DD + d] : 0.f;
    }

    const int ty = tid >> 4, tx = tid & 15;
    const int i0 = ty << 2, j0 = tx << 2;
    const int wid = tid >> 5, lane = tid & 31;

    float oacc[4][4];
    #pragma unroll
    for (int a = 0; a < 4; a++)
        #pragma unroll
        for (int c = 0; c < 4; c++) oacc[a][c] = 0.f;

    for (int kt = 0; kt < (SS + 63) / 64; kt++) {
        const int k0 = kt * 64;
        int nk = SS - k0; if (nk > 64) nk = 64;
        __syncthreads();

        const float* kb = g_qkv + QKV_OFF   + ((size_t)(b * SS + k0)) * DD + h * 64;
        const float* vb = g_qkv + 2*QKV_OFF + ((size_t)(b * SS + k0)) * DD + h * 64;
        #pragma unroll
        for (int r = 0; r < 16; r++) {
            const int idx = tid + r * 256;
            const int j = idx >> 6, d = idx & 63;
            const bool ok = (j < nk);
            Ks[d * ATT_P + j] = ok ? kb[(size_t)j * DD + d] : 0.f;
            Vs[j * ATT_P + d] = ok ? vb[(size_t)j * DD + d] : 0.f;
        }
        __syncthreads();

        float sacc[4][4];
        #pragma unroll
        for (int a = 0; a < 4; a++)
            #pragma unroll
            for (int c = 0; c < 4; c++) sacc[a][c] = 0.f;

        #pragma unroll 4
        for (int d = 0; d < 64; d++) {
            float qv0 = Qs[d * ATT_P + i0 + 0];
            float qv1 = Qs[d * ATT_P + i0 + 1];
            float qv2 = Qs[d * ATT_P + i0 + 2];
            float qv3 = Qs[d * ATT_P + i0 + 3];
            float kv0 = Ks[d * ATT_P + j0 + 0];
            float kv1 = Ks[d * ATT_P + j0 + 1];
            float kv2 = Ks[d * ATT_P + j0 + 2];
            float kv3 = Ks[d * ATT_P + j0 + 3];
            sacc[0][0] += qv0 * kv0; sacc[0][1] += qv0 * kv1; sacc[0][2] += qv0 * kv2; sacc[0][3] += qv0 * kv3;
            sacc[1][0] += qv1 * kv0; sacc[1][1] += qv1 * kv1; sacc[1][2] += qv1 * kv2; sacc[1][3] += qv1 * kv3;
            sacc[2][0] += qv2 * kv0; sacc[2][1] += qv2 * kv1; sacc[2][2] += qv2 * kv2; sacc[2][3] += qv2 * kv3;
            sacc[3][0] += qv3 * kv0; sacc[3][1] += qv3 * kv1; sacc[3][2] += qv3 * kv2; sacc[3][3] += qv3 * kv3;
        }

        #pragma unroll
        for (int ii = 0; ii < 4; ii++) {
            const int qi = i0 + ii;
            const int qg = q0 + qi;
            const bool qok = (qg < SS);
            #pragma unroll
            for (int jj = 0; jj < 4; jj++) {
                const int jl = j0 + jj;
                const int kg = k0 + jl;
                float o;
                if (!qok || jl >= nk) o = -1e30f;
                else {
                    int id;
                    if (qg >= 2 && kg >= 2)
                        id = spd[((size_t)b * LL + (qg - 2)) * LL + (kg - 2)];
                    else
                        id = (qg == kg) ? 0 : 31;
                    o = sacc[ii][jj] * 0.125f + sc[id];
                }
                St[jl * ATT_P + qi] = o;
            }
        }
        __syncthreads();

        // ---- warp-per-row online softmax (8 warps x 8 rows) ----
        for (int rr = 0; rr < 8; rr++) {
            const int i = wid * 8 + rr;
            if (i >= nq) break;
            const int qg = q0 + i;
            if (qg >= limit) {
                St[lane * ATT_P + i]        = (lane      < nk) ? 1.f : 0.f;
                St[(lane + 32) * ATT_P + i] = (lane + 32 < nk) ? 1.f : 0.f;
                if (lane == 0) { rowc[i] = 1.f; rowl[i] += (float)nk; }
            } else {
                float v0 = St[lane * ATT_P + i];
                float v1 = St[(lane + 32) * ATT_P + i];
                float m = fmaxf(v0, v1);
                #pragma unroll
                for (int off = 16; off > 0; off >>= 1)
                    m = fmaxf(m, __shfl_xor_sync(0xffffffffu, m, off));
                const float pm = rowm[i];
                const float mt = fmaxf(m, pm);
                const float p0 = __expf(v0 - mt);
                const float p1 = __expf(v1 - mt);
                St[lane * ATT_P + i]        = p0;
                St[(lane + 32) * ATT_P + i] = p1;
                float s = p0 + p1;
                #pragma unroll
                for (int off = 16; off > 0; off >>= 1)
                    s += __shfl_xor_sync(0xffffffffu, s, off);
                if (lane == 0) {
                    const float corr = __expf(pm - mt);
                    rowl[i] = rowl[i] * corr + s;
                    rowm[i] = mt;
                    rowc[i] = corr;
                }
            }
        }
        __syncthreads();

        float cr0 = rowc[i0 + 0], cr1 = rowc[i0 + 1], cr2 = rowc[i0 + 2], cr3 = rowc[i0 + 3];
        #pragma unroll
        for (int c = 0; c < 4; c++) {
            oacc[0][c] *= cr0; oacc[1][c] *= cr1; oacc[2][c] *= cr2; oacc[3][c] *= cr3;
        }
        #pragma unroll 4
        for (int j = 0; j < 64; j++) {
            float p0 = St[j * ATT_P + i0 + 0];
            float p1 = St[j * ATT_P + i0 + 1];
            float p2 = St[j * ATT_P + i0 + 2];
            float p3 = St[j * ATT_P + i0 + 3];
            float v0 = Vs[j * ATT_P + j0 + 0];
            float v1 = Vs[j * ATT_P + j0 + 1];
            float v2 = Vs[j * ATT_P + j0 + 2];
            float v3 = Vs[j * ATT_P + j0 + 3];
            oacc[0][0] += p0 * v0; oacc[0][1] += p0 * v1; oacc[0][2] += p0 * v2; oacc[0][3] += p0 * v3;
            oacc[1][0] += p1 * v0; oacc[1][1] += p1 * v1; oacc[1][2] += p1 * v2; oacc[1][3] += p1 * v3;
            oacc[2][0] += p2 * v0; oacc[2][1] += p2 * v1; oacc[2][2] += p2 * v2; oacc[2][3] += p2 * v3;
            oacc[3][0] += p3 * v0; oacc[3][1] += p3 * v1; oacc[3][2] += p3 * v2; oacc[3][3] += p3 * v3;
        }
    }

    #pragma unroll
    for (int ii = 0; ii < 4; ii++) {
        const int qi = i0 + ii;
        if (qi < nq) {
            const int qg = q0 + qi;
            const float inv = 1.f / rowl[qi];
            float* ob = g_att + ((size_t)(b * SS + qg)) * DD + h * 64 + j0;
            #pragma unroll
            for (int jj = 0; jj < 4; jj++) ob[jj] = tf32f(oacc[ii][jj] * inv);
        }
    }
}

// ---------------- host driver ----------------
extern "C" void kernel_launch(void* const* d_in, const int* in_sizes, int n_in,
                              void* d_out, int out_size)
{
    const float* graph   = (const float*)d_in[0];
    const float* infeat  = (const float*)d_in[1];
    const float* projW   = (const float*)d_in[2];
    const float* projb   = (const float*)d_in[3];
    const float* sos     = (const float*)d_in[4];
    const float* nodee   = (const float*)d_in[5];
    const float* typee   = (const float*)d_in[6];
    const float* pose    = (const float*)d_in[7];
    const float* spde    = (const float*)d_in[8];
    const float* anorm   = (const float*)d_in[9];
    const float* wq      = (const float*)d_in[10];
    const float* wk      = (const float*)d_in[11];
    const float* wv      = (const float*)d_in[12];
    const float* wo      = (const float*)d_in[13];
    const float* fnorm   = (const float*)d_in[14];
    const float* w1      = (const float*)d_in[15];
    const float* w2      = (const float*)d_in[16];
    const float* w3      = (const float*)d_in[17];
    const float* finaln  = (const float*)d_in[18];
    const float* outW    = (const float*)d_in[19];
    const float* outb    = (const float*)d_in[20];
    const int*   sub     = (const int*)d_in[21];
    const int*   tml     = (const int*)d_in[22];
    const int*   spdidx  = (const int*)d_in[23];
    (void)in_sizes; (void)n_in; (void)out_size;

    float *ph, *px, *pqkv, *patt, *pffn, *pwt;
    cudaGetSymbolAddress((void**)&ph,   g_h);
    cudaGetSymbolAddress((void**)&px,   g_x);
    cudaGetSymbolAddress((void**)&pqkv, g_qkv);
    cudaGetSymbolAddress((void**)&patt, g_att);
    cudaGetSymbolAddress((void**)&pffn, g_ffn);
    cudaGetSymbolAddress((void**)&pwt,  g_wt);
    float* pq = pqkv;
    float* pk = pqkv + QKV_OFF;
    float* pv = pqkv + 2*QKV_OFF;
    float* pt1 = pffn;
    float* pt3 = pffn + FFN_OFF;

    const int attSmem = ATT_SMEM_FLOATS * (int)sizeof(float);
    cudaFuncSetAttribute(attn_k, cudaFuncAttributeMaxDynamicSharedMemorySize, attSmem);
    const int SM2 = STAGES * (2*32*AST*4 + 16*BSTF*4);   // 55296
    const int SM4 = STAGES * (4*32*AST*4 + 16*BSTF*4);   // 75776
    cudaFuncSetAttribute(gemm_tc<2>, cudaFuncAttributeMaxDynamicSharedMemorySize, SM2);
    cudaFuncSetAttribute(gemm_tc<4>, cudaFuncAttributeMaxDynamicSharedMemorySize, SM4);

    // ---- round all gmem GEMM operands to tf32 bit patterns (once per launch) ----
    auto cvt = [&](const float* src, int off, int n) {
        cvt_k<<<2048, 256>>>((const float4*)src, (float4*)(pwt + off), n / 4);
    };
    cvt(infeat, OFF_INF,  N_INF);
    cvt(projW,  OFF_PROJ, N_PROJ);
    cvt(wq,     OFF_WQ,   N_W4);
    cvt(wk,     OFF_WK,   N_W4);
    cvt(wv,     OFF_WV,   N_W4);
    cvt(wo,     OFF_WO,   N_W4);
    cvt(w1,     OFF_W1,   N_WF);
    cvt(w3,     OFF_W3,   N_WF);
    cvt(w2,     OFF_W2,   N_WF);
    cvt(outW,   OFF_OUTW, N_OUTW);

    auto gemm = [&](const float* A, const float* W, float* C, const float* E,
                    int M, int N, int K, int mode, int arm) {
        dim3 g((N + 127) / 128, (M + 127) / 128);
        gemm_tc<4><<<g, 256, SM4>>>(A, W, C, E, M, N, K, mode, arm);
    };
    auto gemmS = [&](const float* A, const float* W, float* C, const float* E,
                     int M, int N, int K, int mode, int arm) {
        dim3 g((N + 127) / 128, (M + 63) / 64);
        gemm_tc<2><<<g, 256, SM2>>>(A, W, C, E, M, N, K, mode, arm);
    };

    // input projection (bias fused) into g_x, then embeddings into g_h
    gemmS(pwt + OFF_INF, pwt + OFF_PROJ, px, projb, BB * LL, DD, FDIM, 1, 0);
    embed_k<<<MROWS, 256>>>(graph, sos, nodee, typee, pose, sub);

    for (int i = 0; i < NLAYER; i++) {
        const size_t wOff = (size_t)i * DD * DD;
        const size_t fOff = (size_t)i * DD * DFF;

        rmsnorm_k<<<MROWS, 256>>>(ph, anorm + (size_t)i * DD, px);
        gemmS(px, pwt + OFF_WQ + wOff, pq, nullptr, MROWS, DD, DD, 0, 0);
        gemmS(px, pwt + OFF_WK + wOff, pk, nullptr, MROWS, DD, DD, 0, 0);
        gemmS(px, pwt + OFF_WV + wOff, pv, nullptr, MROWS, DD, DD, 0, 0);

        vmean_k<<<dim3(HH, BB), 256>>>();
        attn_k<<<dim3((SS + 63) / 64, HH, BB), 256, attSmem>>>(spdidx, spde, tml);

        gemmS(patt, pwt + OFF_WO + wOff, ph, nullptr, MROWS, DD, DD, 2, 0);

        rmsnorm_k<<<MROWS, 256>>>(ph, fnorm + (size_t)i * DD, px);
        gemm(px, pwt + OFF_W1 + fOff, pt1, nullptr, MROWS, DFF, DD, 0, 0);
        gemm(px, pwt + OFF_W3 + fOff, pt3, pt1,     MROWS, DFF, DD, 3, 0);
        gemmS(pt3, pwt + OFF_W2 + fOff, ph, nullptr, MROWS, DD, DFF, 2, 0);
    }

    rmsnorm_k<<<MROWS, 256>>>(ph, finaln, px);
    gemm(px, pwt + OFF_OUTW, (float*)d_out, outb, OUTROWS, NVOC, DD, 1, 1);
}